// round 3
// baseline (speedup 1.0000x reference)
#include <cuda_runtime.h>

// Problem constants
#define BQ 4
#define NQ 2048
#define DQ 512
#define PQ 16
#define KQ 4
#define KDQ (KQ*DQ)

// field kernel tiling
#define JT 32          // j-tile (keys per stage)
#define IT 32          // i-tile (queries per block)
#define NT (NQ/JT)     // 64 stages

// Scratch: proj[b][k][j][d], field[b][k][i][d]  (each 64 MB fp32)
__device__ float g_proj [BQ*KQ*NQ*DQ];
__device__ float g_field[BQ*KQ*NQ*DQ];

// ---------------------------------------------------------------------------
// cp.async helpers
// ---------------------------------------------------------------------------
__device__ __forceinline__ unsigned smem_u32(const void* p) {
    return (unsigned)__cvta_generic_to_shared(p);
}
__device__ __forceinline__ void cp16(unsigned dst, const void* src) {
    asm volatile("cp.async.cg.shared.global [%0], [%1], 16;" :: "r"(dst), "l"(src));
}
__device__ __forceinline__ void cp_commit() {
    asm volatile("cp.async.commit_group;");
}
__device__ __forceinline__ void cp_wait0() {
    asm volatile("cp.async.wait_group 0;");
}

// ---------------------------------------------------------------------------
// Kernel A: projection GEMM.  proj[b,k,j,d] = sum_c charge[b,j,c] * Wch[k*D+d, c]
// 128x128 tile, kstep 8, 256 threads, 8x8 per thread.  (unchanged, passing)
// ---------------------------------------------------------------------------
__global__ __launch_bounds__(256) void proj_gemm_kernel(
    const float* __restrict__ charge, const float* __restrict__ Wch)
{
    const int b  = blockIdx.z;
    const int j0 = blockIdx.x * 128;
    const int n0 = blockIdx.y * 128;   // kd tile base
    const int t  = threadIdx.x;
    const int tx = t & 15, ty = t >> 4;

    __shared__ float As[8][128];
    __shared__ float Bs[8][128];

    float acc[8][8];
#pragma unroll
    for (int r = 0; r < 8; r++)
#pragma unroll
        for (int q = 0; q < 8; q++) acc[r][q] = 0.0f;

    const float* Abase = charge + (b*NQ + j0)*DQ;

    for (int c0 = 0; c0 < DQ; c0 += 8) {
        {
            int jj = t >> 1, cgp = t & 1;
            float4 v = *(const float4*)(Abase + jj*DQ + c0 + cgp*4);
            As[cgp*4+0][jj] = v.x; As[cgp*4+1][jj] = v.y;
            As[cgp*4+2][jj] = v.z; As[cgp*4+3][jj] = v.w;
        }
        {
            int kdj = t & 127, cgp = t >> 7;
            float4 v = *(const float4*)(Wch + (n0+kdj)*DQ + c0 + cgp*4);
            Bs[cgp*4+0][kdj] = v.x; Bs[cgp*4+1][kdj] = v.y;
            Bs[cgp*4+2][kdj] = v.z; Bs[cgp*4+3][kdj] = v.w;
        }
        __syncthreads();
#pragma unroll
        for (int kk = 0; kk < 8; kk++) {
            float a[8], bb[8];
            *(float4*)&a[0]  = *(const float4*)&As[kk][ty*8];
            *(float4*)&a[4]  = *(const float4*)&As[kk][ty*8+4];
            *(float4*)&bb[0] = *(const float4*)&Bs[kk][tx*4];
            *(float4*)&bb[4] = *(const float4*)&Bs[kk][64 + tx*4];
#pragma unroll
            for (int r = 0; r < 8; r++)
#pragma unroll
                for (int q = 0; q < 8; q++)
                    acc[r][q] += a[r]*bb[q];
        }
        __syncthreads();
    }

    const int c1 = n0 + tx*4;
    const int c2 = c1 + 64;
    const int k1 = c1 >> 9, d1 = c1 & 511;
    const int k2 = c2 >> 9, d2 = c2 & 511;
#pragma unroll
    for (int r = 0; r < 8; r++) {
        int j = j0 + ty*8 + r;
        *(float4*)(g_proj + ((b*KQ + k1)*NQ + j)*DQ + d1) =
            make_float4(acc[r][0], acc[r][1], acc[r][2], acc[r][3]);
        *(float4*)(g_proj + ((b*KQ + k2)*NQ + j)*DQ + d2) =
            make_float4(acc[r][4], acc[r][5], acc[r][6], acc[r][7]);
    }
}

// ---------------------------------------------------------------------------
// Kernel B v2: field[b,k,i,d] = sum_j exp(-d2(i,j)*ck)*mass[j] * proj[b,k,j,d]
// Block = (b, k, i-tile 32) x full D=512. 512 threads, 4x8 acc per thread.
// Double-buffered cp.async pipeline; weight computation (MUFU exp) interleaved
// between MMA halves so it hides under FFMA; query positions in registers.
// Dynamic smem ~140 KB.
// ---------------------------------------------------------------------------
__global__ __launch_bounds__(512) void field_kernel(
    const float* __restrict__ position, const float* __restrict__ mass,
    const float* __restrict__ lbw)
{
    extern __shared__ float sm[];
    float* projS = sm;                           // 2 * JT * 512
    float* posJS = projS + 2*JT*DQ;              // 2 * JT * 16
    float* massS = posJS + 2*JT*PQ;              // 2 * JT
    float* wS    = massS + 2*JT;                 // 2 * JT * IT   (wS[j][i])

    const int b  = blockIdx.z;
    const int k  = blockIdx.y;
    const int i0 = blockIdx.x * IT;
    const int t  = threadIdx.x;
    const int rg = t >> 6;      // 0..7 -> rows rg*4 + r
    const int cg = t & 63;      // cols cg*4 and 256+cg*4

    const float bw   = __expf(lbw[k]);
    const float negc = -1.0f / (2.0f*bw + 1e-8f);

    // Each thread owns query i_w = t & 31 for weight generation — posI in regs.
    const int i_w = t & 31;
    const int j_w = t >> 5;     // 0..15 (second pass adds 16)
    float pi[16];
    {
        const float4* src = (const float4*)(position + (size_t)(b*NQ + i0 + i_w)*PQ);
#pragma unroll
        for (int q = 0; q < 4; q++) {
            float4 v = src[q];
            pi[q*4+0] = v.x; pi[q*4+1] = v.y; pi[q*4+2] = v.z; pi[q*4+3] = v.w;
        }
    }

    const float* projBase = g_proj + (size_t)(b*KQ + k)*NQ*DQ;

    // ---- tile loaders -----------------------------------------------------
    auto load_tile = [&](int buf, int jt) {
        const int j0 = jt*JT;
        {   // proj tile: 32 x 512 floats, 128B per thread
            int row = t >> 4;              // 0..31
            int col = (t & 15) * 32;       // 0..480
            const float* src = projBase + (size_t)(j0 + row)*DQ + col;
            unsigned dst = smem_u32(projS + buf*JT*DQ + row*DQ + col);
#pragma unroll
            for (int u = 0; u < 8; u++)
                cp16(dst + u*16, src + u*4);
        }
        if (t < 128) {                     // key positions: 32 x 16 floats
            int j = t >> 2, q = (t & 3)*4;
            cp16(smem_u32(posJS + buf*JT*PQ + j*PQ + q),
                 position + (size_t)(b*NQ + j0 + j)*PQ + q);
        }
        if (t < 8) {                       // mass: 32 floats
            cp16(smem_u32(massS + buf*JT + t*4),
                 mass + (size_t)b*NQ + j0 + t*4);
        }
        cp_commit();
    };

    auto compute_w = [&](int buf) {
#pragma unroll
        for (int pass = 0; pass < 2; pass++) {
            int j = j_w + pass*16;
            const float* pj = posJS + buf*JT*PQ + j*PQ;
            float d2 = 0.0f;
#pragma unroll
            for (int q = 0; q < 4; q++) {
                float4 v = *(const float4*)(pj + q*4);
                float d0 = pi[q*4+0] - v.x;
                float d1 = pi[q*4+1] - v.y;
                float dd2 = pi[q*4+2] - v.z;
                float d3 = pi[q*4+3] - v.w;
                d2 = fmaf(d0, d0, d2); d2 = fmaf(d1, d1, d2);
                d2 = fmaf(dd2, dd2, d2); d2 = fmaf(d3, d3, d2);
            }
            wS[buf*JT*IT + j*IT + i_w] = __expf(d2*negc) * massS[buf*JT + j];
        }
    };

    float acc[4][8];
#pragma unroll
    for (int r = 0; r < 4; r++)
#pragma unroll
        for (int q = 0; q < 8; q++) acc[r][q] = 0.0f;

    auto mma_half = [&](int buf, int lo) {
        const float* pW = wS    + buf*JT*IT;
        const float* pP = projS + buf*JT*DQ;
#pragma unroll
        for (int u = 0; u < 16; u++) {
            int jj = lo + u;
            float4 wv = *(const float4*)(pW + jj*IT + rg*4);
            float4 p0 = *(const float4*)(pP + jj*DQ + cg*4);
            float4 p1 = *(const float4*)(pP + jj*DQ + 256 + cg*4);
            float w0 = wv.x, w1 = wv.y, w2 = wv.z, w3 = wv.w;
            acc[0][0] = fmaf(w0, p0.x, acc[0][0]); acc[0][1] = fmaf(w0, p0.y, acc[0][1]);
            acc[0][2] = fmaf(w0, p0.z, acc[0][2]); acc[0][3] = fmaf(w0, p0.w, acc[0][3]);
            acc[0][4] = fmaf(w0, p1.x, acc[0][4]); acc[0][5] = fmaf(w0, p1.y, acc[0][5]);
            acc[0][6] = fmaf(w0, p1.z, acc[0][6]); acc[0][7] = fmaf(w0, p1.w, acc[0][7]);
            acc[1][0] = fmaf(w1, p0.x, acc[1][0]); acc[1][1] = fmaf(w1, p0.y, acc[1][1]);
            acc[1][2] = fmaf(w1, p0.z, acc[1][2]); acc[1][3] = fmaf(w1, p0.w, acc[1][3]);
            acc[1][4] = fmaf(w1, p1.x, acc[1][4]); acc[1][5] = fmaf(w1, p1.y, acc[1][5]);
            acc[1][6] = fmaf(w1, p1.z, acc[1][6]); acc[1][7] = fmaf(w1, p1.w, acc[1][7]);
            acc[2][0] = fmaf(w2, p0.x, acc[2][0]); acc[2][1] = fmaf(w2, p0.y, acc[2][1]);
            acc[2][2] = fmaf(w2, p0.z, acc[2][2]); acc[2][3] = fmaf(w2, p0.w, acc[2][3]);
            acc[2][4] = fmaf(w2, p1.x, acc[2][4]); acc[2][5] = fmaf(w2, p1.y, acc[2][5]);
            acc[2][6] = fmaf(w2, p1.z, acc[2][6]); acc[2][7] = fmaf(w2, p1.w, acc[2][7]);
            acc[3][0] = fmaf(w3, p0.x, acc[3][0]); acc[3][1] = fmaf(w3, p0.y, acc[3][1]);
            acc[3][2] = fmaf(w3, p0.z, acc[3][2]); acc[3][3] = fmaf(w3, p0.w, acc[3][3]);
            acc[3][4] = fmaf(w3, p1.x, acc[3][4]); acc[3][5] = fmaf(w3, p1.y, acc[3][5]);
            acc[3][6] = fmaf(w3, p1.z, acc[3][6]); acc[3][7] = fmaf(w3, p1.w, acc[3][7]);
        }
    };

    // ---- pipeline ----------------------------------------------------------
    load_tile(0, 0);
    cp_wait0();
    __syncthreads();
    compute_w(0);

    for (int jt = 0; jt < NT; jt++) {
        const int cur = jt & 1, nxt = cur ^ 1;
        __syncthreads();                    // wS[cur] visible; buf nxt free (prev readers done)
        if (jt + 1 < NT) load_tile(nxt, jt + 1);
        mma_half(cur, 0);
        if (jt + 1 < NT) {
            cp_wait0();
            __syncthreads();                // posJS/projS[nxt] visible to all
            compute_w(nxt);
        }
        mma_half(cur, 16);
    }

    float* fBase = g_field + (size_t)((b*KQ + k)*NQ + i0) * DQ;
#pragma unroll
    for (int r = 0; r < 4; r++) {
        int row = rg*4 + r;
        *(float4*)(fBase + row*DQ + cg*4) =
            make_float4(acc[r][0], acc[r][1], acc[r][2], acc[r][3]);
        *(float4*)(fBase + row*DQ + 256 + cg*4) =
            make_float4(acc[r][4], acc[r][5], acc[r][6], acc[r][7]);
    }
}

// ---------------------------------------------------------------------------
// Kernel C: out[b,i,:] = LN( sum_kd field[b,i,kd] * Wcb[dout,kd] ) * gamma + beta
// (unchanged, passing)
// ---------------------------------------------------------------------------
__global__ __launch_bounds__(256) void combine_ln_kernel(
    const float* __restrict__ Wcb, const float* __restrict__ gammaP,
    const float* __restrict__ betaP, float* __restrict__ out)
{
    const int b  = blockIdx.y;
    const int i0 = blockIdx.x * 32;
    const int t  = threadIdx.x;
    const int rg = t >> 6;
    const int cg = t & 63;

    __shared__ float fieldT[16*40];
    __shared__ float WcS[16*516];
    __shared__ float meanS[32], rsS[32];
    __shared__ float gammaS[512], betaS[512];

    for (int u = t; u < 512; u += 256) { gammaS[u] = gammaP[u]; betaS[u] = betaP[u]; }

    float acc[8][8];
#pragma unroll
    for (int r = 0; r < 8; r++)
#pragma unroll
        for (int q = 0; q < 8; q++) acc[r][q] = 0.0f;

    for (int kt = 0; kt < KDQ/16; kt++) {
        const int kd0 = kt*16;
        const int k   = kd0 >> 9;
        const int d0  = kd0 & 511;
        __syncthreads();
#pragma unroll
        for (int m = 0; m < 2; m++) {
            int u = t + m*256;
            int i = u >> 4, kk = u & 15;
            fieldT[kk*40 + i] = g_field[((size_t)(b*KQ + k)*NQ + i0 + i)*DQ + d0 + kk];
        }
#pragma unroll
        for (int m = 0; m < 8; m++) {
            int u = t + m*256;
            int dout = u >> 2, q = u & 3;
            float4 v = *(const float4*)(Wcb + dout*KDQ + kd0 + q*4);
            WcS[(q*4+0)*516 + dout] = v.x;
            WcS[(q*4+1)*516 + dout] = v.y;
            WcS[(q*4+2)*516 + dout] = v.z;
            WcS[(q*4+3)*516 + dout] = v.w;
        }
        __syncthreads();
#pragma unroll
        for (int kk = 0; kk < 16; kk++) {
            float a[8], bb[8];
            *(float4*)&a[0]  = *(const float4*)&fieldT[kk*40 + rg*8];
            *(float4*)&a[4]  = *(const float4*)&fieldT[kk*40 + rg*8 + 4];
            *(float4*)&bb[0] = *(const float4*)&WcS[kk*516 + cg*4];
            *(float4*)&bb[4] = *(const float4*)&WcS[kk*516 + 256 + cg*4];
#pragma unroll
            for (int r = 0; r < 8; r++)
#pragma unroll
                for (int q = 0; q < 8; q++)
                    acc[r][q] += a[r]*bb[q];
        }
    }

    __syncthreads();
    float* rowSum = WcS;
    float* rowSq  = WcS + 2048;
#pragma unroll
    for (int r = 0; r < 8; r++) {
        float s = 0.0f, s2 = 0.0f;
#pragma unroll
        for (int q = 0; q < 8; q++) { s += acc[r][q]; s2 += acc[r][q]*acc[r][q]; }
        int row = rg*8 + r;
        rowSum[row*64 + cg] = s;
        rowSq [row*64 + cg] = s2;
    }
    __syncthreads();
    {
        int w = t >> 5, lane = t & 31;
#pragma unroll
        for (int rr = 0; rr < 4; rr++) {
            int row = w*4 + rr;
            float s  = rowSum[row*64 + lane] + rowSum[row*64 + lane + 32];
            float s2 = rowSq [row*64 + lane] + rowSq [row*64 + lane + 32];
#pragma unroll
            for (int off = 16; off > 0; off >>= 1) {
                s  += __shfl_xor_sync(0xffffffffu, s,  off);
                s2 += __shfl_xor_sync(0xffffffffu, s2, off);
            }
            if (lane == 0) {
                float mean = s * (1.0f/512.0f);
                float var  = s2 * (1.0f/512.0f) - mean*mean;
                meanS[row] = mean;
                rsS[row]   = rsqrtf(var + 1e-5f);
            }
        }
    }
    __syncthreads();
#pragma unroll
    for (int r = 0; r < 8; r++) {
        int row = rg*8 + r;
        float m  = meanS[row];
        float rs = rsS[row];
        float o[8];
#pragma unroll
        for (int q = 0; q < 4; q++) {
            int col = cg*4 + q;
            o[q]   = (acc[r][q]   - m)*rs*gammaS[col]       + betaS[col];
            o[q+4] = (acc[r][q+4] - m)*rs*gammaS[col + 256] + betaS[col + 256];
        }
        float* dst = out + (size_t)(b*NQ + i0 + row)*DQ;
        *(float4*)(dst + cg*4)       = make_float4(o[0], o[1], o[2], o[3]);
        *(float4*)(dst + 256 + cg*4) = make_float4(o[4], o[5], o[6], o[7]);
    }
}

// ---------------------------------------------------------------------------
extern "C" void kernel_launch(void* const* d_in, const int* in_sizes, int n_in,
                              void* d_out, int out_size)
{
    const float* charge   = (const float*)d_in[0];
    const float* position = (const float*)d_in[1];
    const float* mass     = (const float*)d_in[2];
    const float* lbw      = (const float*)d_in[3];
    const float* Wch      = (const float*)d_in[4];
    const float* Wcb      = (const float*)d_in[5];
    const float* gammaP   = (const float*)d_in[6];
    const float* betaP    = (const float*)d_in[7];
    float* out = (float*)d_out;

    const int smemBytes = (2*(JT*DQ + JT*PQ + JT + JT*IT)) * sizeof(float);
    cudaFuncSetAttribute(field_kernel,
                         cudaFuncAttributeMaxDynamicSharedMemorySize, smemBytes);

    proj_gemm_kernel <<<dim3(NQ/128, KDQ/128, BQ), 256>>>(charge, Wch);
    field_kernel     <<<dim3(NQ/IT, KQ, BQ), 512, smemBytes>>>(position, mass, lbw);
    combine_ln_kernel<<<dim3(NQ/32, BQ), 256>>>(Wcb, gammaP, betaP, out);
}

// round 5
// speedup vs baseline: 1.5731x; 1.5731x over previous
#include <cuda_runtime.h>
#include <cuda_bf16.h>
#include <cstdint>

// Problem constants
#define BQ 4
#define NQ 2048
#define DQ 512
#define PQ 16
#define KQ 4
#define KDQ (KQ*DQ)

// Scratch
__device__ float g_proj [BQ*KQ*NQ*DQ];
__device__ float g_field[BQ*KQ*NQ*DQ];
__device__ __nv_bfloat16 g_pT_hi[(size_t)BQ*KQ*DQ*NQ];   // [bk][d][j]  (mass folded in)
__device__ __nv_bfloat16 g_pT_lo[(size_t)BQ*KQ*DQ*NQ];

// ---------------------------------------------------------------------------
// helpers (portable PTX only: cp.async / ldmatrix / mma.sync — sm_80+ baseline)
// ---------------------------------------------------------------------------
__device__ __forceinline__ unsigned smem_u32(const void* p) {
    return (unsigned)__cvta_generic_to_shared(p);
}
__device__ __forceinline__ void cp16(unsigned dst, const void* src) {
    asm volatile("cp.async.cg.shared.global [%0], [%1], 16;" :: "r"(dst), "l"(src));
}
__device__ __forceinline__ void cp_commit() { asm volatile("cp.async.commit_group;"); }
__device__ __forceinline__ void cp_wait0()  { asm volatile("cp.async.wait_group 0;"); }

__device__ __forceinline__ unsigned sw128(unsigned o) {   // SW128: bits[6:4] ^= bits[9:7]
    return o ^ ((o >> 3) & 0x70u);
}

__device__ __forceinline__ void ldmx4(uint32_t* r, unsigned addr) {
    asm volatile("ldmatrix.sync.aligned.m8n8.x4.shared.b16 {%0,%1,%2,%3}, [%4];"
                 : "=r"(r[0]), "=r"(r[1]), "=r"(r[2]), "=r"(r[3]) : "r"(addr));
}

__device__ __forceinline__ void mma_bf16(float* c, const uint32_t* a,
                                         uint32_t b0, uint32_t b1) {
    asm volatile("mma.sync.aligned.m16n8k16.row.col.f32.bf16.bf16.f32 "
                 "{%0,%1,%2,%3}, {%4,%5,%6,%7}, {%8,%9}, {%0,%1,%2,%3};"
                 : "+f"(c[0]), "+f"(c[1]), "+f"(c[2]), "+f"(c[3])
                 : "r"(a[0]), "r"(a[1]), "r"(a[2]), "r"(a[3]), "r"(b0), "r"(b1));
}

// field kernel smem layout (bytes): W 2x16KB | P 2x16KB | posJ 2x2KB
#define SM_W   0
#define SM_P   32768
#define SM_PJ  65536
#define SMEM_FIELD 69632

// ---------------------------------------------------------------------------
// Kernel A: projection GEMM (unchanged, passing @405us)
// ---------------------------------------------------------------------------
__global__ __launch_bounds__(256) void proj_gemm_kernel(
    const float* __restrict__ charge, const float* __restrict__ Wch)
{
    const int b  = blockIdx.z;
    const int j0 = blockIdx.x * 128;
    const int n0 = blockIdx.y * 128;
    const int t  = threadIdx.x;
    const int tx = t & 15, ty = t >> 4;

    __shared__ float As[8][128];
    __shared__ float Bs[8][128];

    float acc[8][8];
#pragma unroll
    for (int r = 0; r < 8; r++)
#pragma unroll
        for (int q = 0; q < 8; q++) acc[r][q] = 0.0f;

    const float* Abase = charge + (b*NQ + j0)*DQ;

    for (int c0 = 0; c0 < DQ; c0 += 8) {
        {
            int jj = t >> 1, cgp = t & 1;
            float4 v = *(const float4*)(Abase + jj*DQ + c0 + cgp*4);
            As[cgp*4+0][jj] = v.x; As[cgp*4+1][jj] = v.y;
            As[cgp*4+2][jj] = v.z; As[cgp*4+3][jj] = v.w;
        }
        {
            int kdj = t & 127, cgp = t >> 7;
            float4 v = *(const float4*)(Wch + (n0+kdj)*DQ + c0 + cgp*4);
            Bs[cgp*4+0][kdj] = v.x; Bs[cgp*4+1][kdj] = v.y;
            Bs[cgp*4+2][kdj] = v.z; Bs[cgp*4+3][kdj] = v.w;
        }
        __syncthreads();
#pragma unroll
        for (int kk = 0; kk < 8; kk++) {
            float a[8], bb[8];
            *(float4*)&a[0]  = *(const float4*)&As[kk][ty*8];
            *(float4*)&a[4]  = *(const float4*)&As[kk][ty*8+4];
            *(float4*)&bb[0] = *(const float4*)&Bs[kk][tx*4];
            *(float4*)&bb[4] = *(const float4*)&Bs[kk][64 + tx*4];
#pragma unroll
            for (int r = 0; r < 8; r++)
#pragma unroll
                for (int q = 0; q < 8; q++)
                    acc[r][q] += a[r]*bb[q];
        }
        __syncthreads();
    }

    const int c1 = n0 + tx*4;
    const int c2 = c1 + 64;
    const int k1 = c1 >> 9, d1 = c1 & 511;
    const int k2 = c2 >> 9, d2 = c2 & 511;
#pragma unroll
    for (int r = 0; r < 8; r++) {
        int j = j0 + ty*8 + r;
        *(float4*)(g_proj + ((b*KQ + k1)*NQ + j)*DQ + d1) =
            make_float4(acc[r][0], acc[r][1], acc[r][2], acc[r][3]);
        *(float4*)(g_proj + ((b*KQ + k2)*NQ + j)*DQ + d2) =
            make_float4(acc[r][4], acc[r][5], acc[r][6], acc[r][7]);
    }
}

// ---------------------------------------------------------------------------
// Kernel A2: transpose + mass-scale + bf16 hi/lo split.
// g_pT_{hi,lo}[bk][d][j] = split(g_proj[bk][j][d] * mass[b][j])
// ---------------------------------------------------------------------------
__global__ __launch_bounds__(256) void split_t_kernel(const float* __restrict__ mass)
{
    __shared__ float tile[32][33];
    const int bk = blockIdx.z;
    const int j0 = blockIdx.x * 32, d0 = blockIdx.y * 32;
    const int tx = threadIdx.x & 31, ty = threadIdx.x >> 5;
    const float* src = g_proj + ((size_t)bk*NQ + j0)*DQ + d0;
#pragma unroll
    for (int r = 0; r < 4; r++)
        tile[r*8+ty][tx] = src[(size_t)(r*8+ty)*DQ + tx];
    __syncthreads();
    const int b = bk >> 2;
    const float mj = mass[(size_t)b*NQ + j0 + tx];
    const size_t ob = ((size_t)bk*DQ + d0)*NQ + j0;
#pragma unroll
    for (int r = 0; r < 4; r++) {
        int d = r*8 + ty;
        float v = tile[tx][d] * mj;
        __nv_bfloat16 h = __float2bfloat16(v);
        __nv_bfloat16 l = __float2bfloat16(v - __bfloat162float(h));
        g_pT_hi[ob + (size_t)d*NQ + tx] = h;
        g_pT_lo[ob + (size_t)d*NQ + tx] = l;
    }
}

// ---------------------------------------------------------------------------
// Kernel B v4 (mma.sync bf16): field[b,k,i,d] = sum_j exp(-d2(i,j)*ck)*m_j*proj[j,d]
// Block: 128(i) x 128(d), K=2048 j in 64 chunks of 32. 256 thr, 8 warps 2x4,
// warp tile 64x32, m16n8k16. W tiles generated in-SM (exp), P tiles cp.async.
// 3-way bf16 split: Whi*Phi + Whi*Plo + Wlo*Phi. Double-buffered.
// ---------------------------------------------------------------------------
__global__ __launch_bounds__(256, 1) void field_mma_kernel(
    const float* __restrict__ position, const float* __restrict__ lbw)
{
    extern __shared__ char smc[];
    const unsigned sb = smem_u32(smc);
    const int t = threadIdx.x, l = t & 31, w = t >> 5;
    const int wm = w & 1, wn = w >> 1;
    const int i0 = blockIdx.x * 128, d0 = blockIdx.y * 128;
    const int bk = blockIdx.z, b = bk >> 2, k = bk & 3;

    const float negc = -1.0f / (2.0f*__expf(lbw[k]) + 1e-8f);

    // query positions in registers: thread owns i = t&127 for W generation
    const int i_w = t & 127;
    const int jg  = t >> 7;          // 0/1: which 16-j half this thread generates
    float pi[16];
    {
        const float* p = position + ((size_t)b*NQ + i0 + i_w)*PQ;
#pragma unroll
        for (int q = 0; q < 16; q += 4) {
            float4 v = *(const float4*)(p + q);
            pi[q] = v.x; pi[q+1] = v.y; pi[q+2] = v.z; pi[q+3] = v.w;
        }
    }

    // ldmatrix lane-offset bases (pre-swizzle byte offsets within a tile)
    const unsigned aOffB = (unsigned)((wm*64 + (l & 15))*128 + (l >> 4)*16);
    const unsigned bRowB = (unsigned)((l & 7) + ((l >> 4) & 1)*8);
    const unsigned bKH   = (unsigned)(((l >> 3) & 1)*16);

    float acc[4][4][4];
#pragma unroll
    for (int a = 0; a < 4; a++)
#pragma unroll
        for (int n = 0; n < 4; n++)
#pragma unroll
            for (int q = 0; q < 4; q++) acc[a][n][q] = 0.0f;

    // ---- producers ---------------------------------------------------------
    auto loadPJ = [&](int c, int buf) {   // 32 x 16 floats
        if (t < 128) {
            int j = t >> 2, q = t & 3;
            cp16(sb + SM_PJ + buf*2048 + (j*PQ + q*4)*4,
                 position + ((size_t)b*NQ + c*32 + j)*PQ + q*4);
        }
    };
    auto loadP = [&](int c, int buf) {    // 128 d-rows x [hi 64B | lo 64B]
        int row = t >> 1, sel = t & 1;
        const __nv_bfloat16* src = (sel ? g_pT_lo : g_pT_hi) +
            ((size_t)bk*DQ + d0 + row)*NQ + c*32;
        unsigned dst = sb + SM_P + buf*16384;
        unsigned base = (unsigned)(row*128 + sel*64);
#pragma unroll
        for (int cc = 0; cc < 4; cc++)
            cp16(dst + sw128(base + cc*16), (const char*)src + cc*16);
    };
    auto genW = [&](int buf) {            // 128 i x [hi 32j | lo 32j] from posJ[buf]
        const float* pj = (const float*)(smc + SM_PJ + buf*2048) + jg*16*PQ;
        char* wb = smc + SM_W + buf*16384;
        uint32_t ph[8], pl[8];
#pragma unroll
        for (int jp = 0; jp < 8; jp++) {
            float wv[2];
#pragma unroll
            for (int u = 0; u < 2; u++) {
                const float* pr = pj + (jp*2 + u)*PQ;
                float d2 = 0.f;
#pragma unroll
                for (int q = 0; q < 16; q += 4) {
                    float4 v = *(const float4*)(pr + q);
                    float a0 = pi[q]-v.x, a1 = pi[q+1]-v.y;
                    float a2 = pi[q+2]-v.z, a3 = pi[q+3]-v.w;
                    d2 = fmaf(a0,a0,d2); d2 = fmaf(a1,a1,d2);
                    d2 = fmaf(a2,a2,d2); d2 = fmaf(a3,a3,d2);
                }
                wv[u] = __expf(d2*negc);
            }
            __nv_bfloat16 h0 = __float2bfloat16(wv[0]);
            __nv_bfloat16 h1 = __float2bfloat16(wv[1]);
            __nv_bfloat16 l0 = __float2bfloat16(wv[0] - __bfloat162float(h0));
            __nv_bfloat16 l1 = __float2bfloat16(wv[1] - __bfloat162float(h1));
            ph[jp] = (uint32_t)__bfloat16_as_ushort(h0) |
                     ((uint32_t)__bfloat16_as_ushort(h1) << 16);
            pl[jp] = (uint32_t)__bfloat16_as_ushort(l0) |
                     ((uint32_t)__bfloat16_as_ushort(l1) << 16);
        }
        unsigned ro = (unsigned)(i_w*128 + jg*32);
        *(uint4*)(wb + sw128(ro))           = make_uint4(ph[0], ph[1], ph[2], ph[3]);
        *(uint4*)(wb + sw128(ro + 16))      = make_uint4(ph[4], ph[5], ph[6], ph[7]);
        *(uint4*)(wb + sw128(ro + 64))      = make_uint4(pl[0], pl[1], pl[2], pl[3]);
        *(uint4*)(wb + sw128(ro + 64 + 16)) = make_uint4(pl[4], pl[5], pl[6], pl[7]);
    };

    // ---- one k-step (16 j) of MMAs on buffer `buf` --------------------------
    auto mma_step = [&](int buf, int ks) {
        const unsigned wbase = sb + SM_W + buf*16384;
        const unsigned pbase = sb + SM_P + buf*16384;
        uint32_t AH[4][4], AL[4][4], BH[2][4], BL[2][4];
#pragma unroll
        for (int mf = 0; mf < 4; mf++) {
            unsigned o = aOffB + mf*2048 + ks*32;
            ldmx4(AH[mf], wbase + sw128(o));
            ldmx4(AL[mf], wbase + sw128(o + 64));
        }
#pragma unroll
        for (int nb = 0; nb < 2; nb++) {
            unsigned o = (bRowB + wn*32 + nb*16)*128 + bKH + ks*32;
            ldmx4(BH[nb], pbase + sw128(o));
            ldmx4(BL[nb], pbase + sw128(o + 64));
        }
#pragma unroll
        for (int mf = 0; mf < 4; mf++)
#pragma unroll
            for (int nb = 0; nb < 2; nb++)
#pragma unroll
                for (int ns = 0; ns < 2; ns++) {
                    float* c = acc[mf][nb*2 + ns];
                    mma_bf16(c, AH[mf], BH[nb][ns*2], BH[nb][ns*2+1]);
                    mma_bf16(c, AH[mf], BL[nb][ns*2], BL[nb][ns*2+1]);
                    mma_bf16(c, AL[mf], BH[nb][ns*2], BH[nb][ns*2+1]);
                }
    };

    // ---- pipeline -----------------------------------------------------------
    loadPJ(0, 0); loadP(0, 0); cp_commit();
    cp_wait0(); __syncthreads();
    genW(0); __syncthreads();

    for (int c = 0; c < 64; c++) {
        const int cur = c & 1, nxt = cur ^ 1;
        if (c < 63) { loadPJ(c+1, nxt); loadP(c+1, nxt); }
        cp_commit();
        mma_step(cur, 0);
        if (c < 63) {
            cp_wait0(); __syncthreads();
            genW(nxt);
        }
        mma_step(cur, 1);
        __syncthreads();
    }

    // ---- epilogue: fragment regs -> gmem ------------------------------------
#pragma unroll
    for (int mf = 0; mf < 4; mf++)
#pragma unroll
        for (int nf = 0; nf < 4; nf++) {
            const float* cc = acc[mf][nf];
            int i = i0 + wm*64 + mf*16 + (l >> 2);
            int d = d0 + wn*32 + nf*8 + (l & 3)*2;
            float* dst = g_field + ((size_t)bk*NQ + i)*DQ + d;
            *(float2*)dst            = make_float2(cc[0], cc[1]);
            *(float2*)(dst + 8*DQ)   = make_float2(cc[2], cc[3]);
        }
}

// ---------------------------------------------------------------------------
// Kernel C: combine GEMM + LayerNorm (unchanged, passing)
// ---------------------------------------------------------------------------
__global__ __launch_bounds__(256) void combine_ln_kernel(
    const float* __restrict__ Wcb, const float* __restrict__ gammaP,
    const float* __restrict__ betaP, float* __restrict__ out)
{
    const int b  = blockIdx.y;
    const int i0 = blockIdx.x * 32;
    const int t  = threadIdx.x;
    const int rg = t >> 6;
    const int cg = t & 63;

    __shared__ float fieldT[16*40];
    __shared__ float WcS[16*516];
    __shared__ float meanS[32], rsS[32];
    __shared__ float gammaS[512], betaS[512];

    for (int u = t; u < 512; u += 256) { gammaS[u] = gammaP[u]; betaS[u] = betaP[u]; }

    float acc[8][8];
#pragma unroll
    for (int r = 0; r < 8; r++)
#pragma unroll
        for (int q = 0; q < 8; q++) acc[r][q] = 0.0f;

    for (int kt = 0; kt < KDQ/16; kt++) {
        const int kd0 = kt*16;
        const int k   = kd0 >> 9;
        const int d0  = kd0 & 511;
        __syncthreads();
#pragma unroll
        for (int m = 0; m < 2; m++) {
            int u = t + m*256;
            int i = u >> 4, kk = u & 15;
            fieldT[kk*40 + i] = g_field[((size_t)(b*KQ + k)*NQ + i0 + i)*DQ + d0 + kk];
        }
#pragma unroll
        for (int m = 0; m < 8; m++) {
            int u = t + m*256;
            int dout = u >> 2, q = u & 3;
            float4 v = *(const float4*)(Wcb + dout*KDQ + kd0 + q*4);
            WcS[(q*4+0)*516 + dout] = v.x;
            WcS[(q*4+1)*516 + dout] = v.y;
            WcS[(q*4+2)*516 + dout] = v.z;
            WcS[(q*4+3)*516 + dout] = v.w;
        }
        __syncthreads();
#pragma unroll
        for (int kk = 0; kk < 16; kk++) {
            float a[8], bb[8];
            *(float4*)&a[0]  = *(const float4*)&fieldT[kk*40 + rg*8];
            *(float4*)&a[4]  = *(const float4*)&fieldT[kk*40 + rg*8 + 4];
            *(float4*)&bb[0] = *(const float4*)&WcS[kk*516 + cg*4];
            *(float4*)&bb[4] = *(const float4*)&WcS[kk*516 + 256 + cg*4];
#pragma unroll
            for (int r = 0; r < 8; r++)
#pragma unroll
                for (int q = 0; q < 8; q++)
                    acc[r][q] += a[r]*bb[q];
        }
    }

    __syncthreads();
    float* rowSum = WcS;
    float* rowSq  = WcS + 2048;
#pragma unroll
    for (int r = 0; r < 8; r++) {
        float s = 0.0f, s2 = 0.0f;
#pragma unroll
        for (int q = 0; q < 8; q++) { s += acc[r][q]; s2 += acc[r][q]*acc[r][q]; }
        int row = rg*8 + r;
        rowSum[row*64 + cg] = s;
        rowSq [row*64 + cg] = s2;
    }
    __syncthreads();
    {
        int w = t >> 5, lane = t & 31;
#pragma unroll
        for (int rr = 0; rr < 4; rr++) {
            int row = w*4 + rr;
            float s  = rowSum[row*64 + lane] + rowSum[row*64 + lane + 32];
            float s2 = rowSq [row*64 + lane] + rowSq [row*64 + lane + 32];
#pragma unroll
            for (int off = 16; off > 0; off >>= 1) {
                s  += __shfl_xor_sync(0xffffffffu, s,  off);
                s2 += __shfl_xor_sync(0xffffffffu, s2, off);
            }
            if (lane == 0) {
                float mean = s * (1.0f/512.0f);
                float var  = s2 * (1.0f/512.0f) - mean*mean;
                meanS[row] = mean;
                rsS[row]   = rsqrtf(var + 1e-5f);
            }
        }
    }
    __syncthreads();
#pragma unroll
    for (int r = 0; r < 8; r++) {
        int row = rg*8 + r;
        float m  = meanS[row];
        float rs = rsS[row];
        float o[8];
#pragma unroll
        for (int q = 0; q < 4; q++) {
            int col = cg*4 + q;
            o[q]   = (acc[r][q]   - m)*rs*gammaS[col]       + betaS[col];
            o[q+4] = (acc[r][q+4] - m)*rs*gammaS[col + 256] + betaS[col + 256];
        }
        float* dst = out + (size_t)(b*NQ + i0 + row)*DQ;
        *(float4*)(dst + cg*4)       = make_float4(o[0], o[1], o[2], o[3]);
        *(float4*)(dst + 256 + cg*4) = make_float4(o[4], o[5], o[6], o[7]);
    }
}

// ---------------------------------------------------------------------------
extern "C" void kernel_launch(void* const* d_in, const int* in_sizes, int n_in,
                              void* d_out, int out_size)
{
    const float* charge   = (const float*)d_in[0];
    const float* position = (const float*)d_in[1];
    const float* mass     = (const float*)d_in[2];
    const float* lbw      = (const float*)d_in[3];
    const float* Wch      = (const float*)d_in[4];
    const float* Wcb      = (const float*)d_in[5];
    const float* gammaP   = (const float*)d_in[6];
    const float* betaP    = (const float*)d_in[7];
    float* out = (float*)d_out;

    cudaFuncSetAttribute(field_mma_kernel,
                         cudaFuncAttributeMaxDynamicSharedMemorySize, SMEM_FIELD);

    proj_gemm_kernel <<<dim3(NQ/128, KDQ/128, BQ), 256>>>(charge, Wch);
    split_t_kernel   <<<dim3(NQ/32, DQ/32, BQ*KQ), 256>>>(mass);
    field_mma_kernel <<<dim3(NQ/128, DQ/128, BQ*KQ), 256, SMEM_FIELD>>>(position, lbw);
    combine_ln_kernel<<<dim3(NQ/32, BQ), 256>>>(Wcb, gammaP, betaP, out);
}

// round 6
// speedup vs baseline: 1.6426x; 1.0442x over previous
#include <cuda_runtime.h>
#include <cuda_bf16.h>
#include <cstdint>

// Problem constants
#define BQ 4
#define NQ 2048
#define DQ 512
#define PQ 16
#define KQ 4
#define KDQ (KQ*DQ)

// Scratch
__device__ float g_proj [BQ*KQ*NQ*DQ];
__device__ __nv_bfloat16 g_pT_hi[(size_t)BQ*KQ*DQ*NQ];   // [bk][d][j]  (mass folded in)
__device__ __nv_bfloat16 g_pT_lo[(size_t)BQ*KQ*DQ*NQ];
__device__ __nv_bfloat16 g_fh[(size_t)BQ*KQ*NQ*DQ];      // field bf16 hi  [bk][i][d]
__device__ __nv_bfloat16 g_fl[(size_t)BQ*KQ*NQ*DQ];      // field bf16 lo
__device__ __nv_bfloat16 g_cbh[(size_t)DQ*KDQ];          // W_combine hi [dout][kd]
__device__ __nv_bfloat16 g_cbl[(size_t)DQ*KDQ];          // W_combine lo

// ---------------------------------------------------------------------------
// helpers (portable PTX only: cp.async / ldmatrix / mma.sync — sm_80+ baseline)
// ---------------------------------------------------------------------------
__device__ __forceinline__ unsigned smem_u32(const void* p) {
    return (unsigned)__cvta_generic_to_shared(p);
}
__device__ __forceinline__ void cp16(unsigned dst, const void* src) {
    asm volatile("cp.async.cg.shared.global [%0], [%1], 16;" :: "r"(dst), "l"(src));
}
__device__ __forceinline__ void cp_commit() { asm volatile("cp.async.commit_group;"); }
__device__ __forceinline__ void cp_wait0()  { asm volatile("cp.async.wait_group 0;"); }

__device__ __forceinline__ unsigned sw128(unsigned o) {   // SW128: bits[6:4] ^= bits[9:7]
    return o ^ ((o >> 3) & 0x70u);
}
// swizzle for 64-byte rows: segment (16B units within row) XOR'ed by row bits
__device__ __forceinline__ unsigned sw64row(unsigned row, unsigned seg) {
    return row*64u + (seg ^ ((row & 6u) << 3));
}

__device__ __forceinline__ void ldmx4(uint32_t* r, unsigned addr) {
    asm volatile("ldmatrix.sync.aligned.m8n8.x4.shared.b16 {%0,%1,%2,%3}, [%4];"
                 : "=r"(r[0]), "=r"(r[1]), "=r"(r[2]), "=r"(r[3]) : "r"(addr));
}

__device__ __forceinline__ void mma_bf16(float* c, const uint32_t* a,
                                         uint32_t b0, uint32_t b1) {
    asm volatile("mma.sync.aligned.m16n8k16.row.col.f32.bf16.bf16.f32 "
                 "{%0,%1,%2,%3}, {%4,%5,%6,%7}, {%8,%9}, {%0,%1,%2,%3};"
                 : "+f"(c[0]), "+f"(c[1]), "+f"(c[2]), "+f"(c[3])
                 : "r"(a[0]), "r"(a[1]), "r"(a[2]), "r"(a[3]), "r"(b0), "r"(b1));
}

// field kernel smem layout (bytes): W 2x16KB | P 2x16KB | posJ 2x2KB
#define SM_W   0
#define SM_P   32768
#define SM_PJ  65536
#define SMEM_FIELD 69632

// combine kernel smem layout
#define CM_A   0          // 2 x 2KB
#define CM_B   4096       // 2 x 32KB
#define CM_LN  69632      // rowSum 4KB | rowSq 4KB
#define CM_GB  77824      // gamma 2KB | beta 2KB
#define SMEM_COMB 81920

// ---------------------------------------------------------------------------
// Kernel A: projection GEMM (unchanged, passing @405us)
// ---------------------------------------------------------------------------
__global__ __launch_bounds__(256) void proj_gemm_kernel(
    const float* __restrict__ charge, const float* __restrict__ Wch)
{
    const int b  = blockIdx.z;
    const int j0 = blockIdx.x * 128;
    const int n0 = blockIdx.y * 128;
    const int t  = threadIdx.x;
    const int tx = t & 15, ty = t >> 4;

    __shared__ float As[8][128];
    __shared__ float Bs[8][128];

    float acc[8][8];
#pragma unroll
    for (int r = 0; r < 8; r++)
#pragma unroll
        for (int q = 0; q < 8; q++) acc[r][q] = 0.0f;

    const float* Abase = charge + (b*NQ + j0)*DQ;

    for (int c0 = 0; c0 < DQ; c0 += 8) {
        {
            int jj = t >> 1, cgp = t & 1;
            float4 v = *(const float4*)(Abase + jj*DQ + c0 + cgp*4);
            As[cgp*4+0][jj] = v.x; As[cgp*4+1][jj] = v.y;
            As[cgp*4+2][jj] = v.z; As[cgp*4+3][jj] = v.w;
        }
        {
            int kdj = t & 127, cgp = t >> 7;
            float4 v = *(const float4*)(Wch + (n0+kdj)*DQ + c0 + cgp*4);
            Bs[cgp*4+0][kdj] = v.x; Bs[cgp*4+1][kdj] = v.y;
            Bs[cgp*4+2][kdj] = v.z; Bs[cgp*4+3][kdj] = v.w;
        }
        __syncthreads();
#pragma unroll
        for (int kk = 0; kk < 8; kk++) {
            float a[8], bb[8];
            *(float4*)&a[0]  = *(const float4*)&As[kk][ty*8];
            *(float4*)&a[4]  = *(const float4*)&As[kk][ty*8+4];
            *(float4*)&bb[0] = *(const float4*)&Bs[kk][tx*4];
            *(float4*)&bb[4] = *(const float4*)&Bs[kk][64 + tx*4];
#pragma unroll
            for (int r = 0; r < 8; r++)
#pragma unroll
                for (int q = 0; q < 8; q++)
                    acc[r][q] += a[r]*bb[q];
        }
        __syncthreads();
    }

    const int c1 = n0 + tx*4;
    const int c2 = c1 + 64;
    const int k1 = c1 >> 9, d1 = c1 & 511;
    const int k2 = c2 >> 9, d2 = c2 & 511;
#pragma unroll
    for (int r = 0; r < 8; r++) {
        int j = j0 + ty*8 + r;
        *(float4*)(g_proj + ((b*KQ + k1)*NQ + j)*DQ + d1) =
            make_float4(acc[r][0], acc[r][1], acc[r][2], acc[r][3]);
        *(float4*)(g_proj + ((b*KQ + k2)*NQ + j)*DQ + d2) =
            make_float4(acc[r][4], acc[r][5], acc[r][6], acc[r][7]);
    }
}

// ---------------------------------------------------------------------------
// Kernel A2: transpose + mass-scale + bf16 hi/lo split of proj
// ---------------------------------------------------------------------------
__global__ __launch_bounds__(256) void split_t_kernel(const float* __restrict__ mass)
{
    __shared__ float tile[32][33];
    const int bk = blockIdx.z;
    const int j0 = blockIdx.x * 32, d0 = blockIdx.y * 32;
    const int tx = threadIdx.x & 31, ty = threadIdx.x >> 5;
    const float* src = g_proj + ((size_t)bk*NQ + j0)*DQ + d0;
#pragma unroll
    for (int r = 0; r < 4; r++)
        tile[r*8+ty][tx] = src[(size_t)(r*8+ty)*DQ + tx];
    __syncthreads();
    const int b = bk >> 2;
    const float mj = mass[(size_t)b*NQ + j0 + tx];
    const size_t ob = ((size_t)bk*DQ + d0)*NQ + j0;
#pragma unroll
    for (int r = 0; r < 4; r++) {
        int d = r*8 + ty;
        float v = tile[tx][d] * mj;
        __nv_bfloat16 h = __float2bfloat16(v);
        __nv_bfloat16 l = __float2bfloat16(v - __bfloat162float(h));
        g_pT_hi[ob + (size_t)d*NQ + tx] = h;
        g_pT_lo[ob + (size_t)d*NQ + tx] = l;
    }
}

// ---------------------------------------------------------------------------
// Kernel A3: bf16 hi/lo split of W_combine
// ---------------------------------------------------------------------------
__global__ __launch_bounds__(256) void split_cb_kernel(const float* __restrict__ Wcb)
{
    const size_t idx = (size_t)blockIdx.x*1024 + threadIdx.x*4;
    float4 v = *(const float4*)(Wcb + idx);
    float vv[4] = {v.x, v.y, v.z, v.w};
#pragma unroll
    for (int q = 0; q < 4; q++) {
        __nv_bfloat16 h = __float2bfloat16(vv[q]);
        g_cbh[idx + q] = h;
        g_cbl[idx + q] = __float2bfloat16(vv[q] - __bfloat162float(h));
    }
}

// ---------------------------------------------------------------------------
// Kernel B (mma.sync bf16): field[b,k,i,d] = sum_j exp(-d2(i,j)*ck)*m_j*proj[j,d]
// Epilogue now writes bf16 hi/lo split directly to g_fh/g_fl.
// ---------------------------------------------------------------------------
__global__ __launch_bounds__(256, 1) void field_mma_kernel(
    const float* __restrict__ position, const float* __restrict__ lbw)
{
    extern __shared__ char smc[];
    const unsigned sb = smem_u32(smc);
    const int t = threadIdx.x, l = t & 31, w = t >> 5;
    const int wm = w & 1, wn = w >> 1;
    const int i0 = blockIdx.x * 128, d0 = blockIdx.y * 128;
    const int bk = blockIdx.z, b = bk >> 2, k = bk & 3;

    const float negc = -1.0f / (2.0f*__expf(lbw[k]) + 1e-8f);

    const int i_w = t & 127;
    const int jg  = t >> 7;
    float pi[16];
    {
        const float* p = position + ((size_t)b*NQ + i0 + i_w)*PQ;
#pragma unroll
        for (int q = 0; q < 16; q += 4) {
            float4 v = *(const float4*)(p + q);
            pi[q] = v.x; pi[q+1] = v.y; pi[q+2] = v.z; pi[q+3] = v.w;
        }
    }

    const unsigned aOffB = (unsigned)((wm*64 + (l & 15))*128 + (l >> 4)*16);
    const unsigned bRowB = (unsigned)((l & 7) + ((l >> 4) & 1)*8);
    const unsigned bKH   = (unsigned)(((l >> 3) & 1)*16);

    float acc[4][4][4];
#pragma unroll
    for (int a = 0; a < 4; a++)
#pragma unroll
        for (int n = 0; n < 4; n++)
#pragma unroll
            for (int q = 0; q < 4; q++) acc[a][n][q] = 0.0f;

    auto loadPJ = [&](int c, int buf) {
        if (t < 128) {
            int j = t >> 2, q = t & 3;
            cp16(sb + SM_PJ + buf*2048 + (j*PQ + q*4)*4,
                 position + ((size_t)b*NQ + c*32 + j)*PQ + q*4);
        }
    };
    auto loadP = [&](int c, int buf) {
        int row = t >> 1, sel = t & 1;
        const __nv_bfloat16* src = (sel ? g_pT_lo : g_pT_hi) +
            ((size_t)bk*DQ + d0 + row)*NQ + c*32;
        unsigned dst = sb + SM_P + buf*16384;
        unsigned base = (unsigned)(row*128 + sel*64);
#pragma unroll
        for (int cc = 0; cc < 4; cc++)
            cp16(dst + sw128(base + cc*16), (const char*)src + cc*16);
    };
    auto genW = [&](int buf) {
        const float* pj = (const float*)(smc + SM_PJ + buf*2048) + jg*16*PQ;
        char* wb = smc + SM_W + buf*16384;
        uint32_t ph[8], pl[8];
#pragma unroll
        for (int jp = 0; jp < 8; jp++) {
            float wv[2];
#pragma unroll
            for (int u = 0; u < 2; u++) {
                const float* pr = pj + (jp*2 + u)*PQ;
                float d2 = 0.f;
#pragma unroll
                for (int q = 0; q < 16; q += 4) {
                    float4 v = *(const float4*)(pr + q);
                    float a0 = pi[q]-v.x, a1 = pi[q+1]-v.y;
                    float a2 = pi[q+2]-v.z, a3 = pi[q+3]-v.w;
                    d2 = fmaf(a0,a0,d2); d2 = fmaf(a1,a1,d2);
                    d2 = fmaf(a2,a2,d2); d2 = fmaf(a3,a3,d2);
                }
                wv[u] = __expf(d2*negc);
            }
            __nv_bfloat16 h0 = __float2bfloat16(wv[0]);
            __nv_bfloat16 h1 = __float2bfloat16(wv[1]);
            __nv_bfloat16 l0 = __float2bfloat16(wv[0] - __bfloat162float(h0));
            __nv_bfloat16 l1 = __float2bfloat16(wv[1] - __bfloat162float(h1));
            ph[jp] = (uint32_t)__bfloat16_as_ushort(h0) |
                     ((uint32_t)__bfloat16_as_ushort(h1) << 16);
            pl[jp] = (uint32_t)__bfloat16_as_ushort(l0) |
                     ((uint32_t)__bfloat16_as_ushort(l1) << 16);
        }
        unsigned ro = (unsigned)(i_w*128 + jg*32);
        *(uint4*)(wb + sw128(ro))           = make_uint4(ph[0], ph[1], ph[2], ph[3]);
        *(uint4*)(wb + sw128(ro + 16))      = make_uint4(ph[4], ph[5], ph[6], ph[7]);
        *(uint4*)(wb + sw128(ro + 64))      = make_uint4(pl[0], pl[1], pl[2], pl[3]);
        *(uint4*)(wb + sw128(ro + 64 + 16)) = make_uint4(pl[4], pl[5], pl[6], pl[7]);
    };

    auto mma_step = [&](int buf, int ks) {
        const unsigned wbase = sb + SM_W + buf*16384;
        const unsigned pbase = sb + SM_P + buf*16384;
        uint32_t AH[4][4], AL[4][4], BH[2][4], BL[2][4];
#pragma unroll
        for (int mf = 0; mf < 4; mf++) {
            unsigned o = aOffB + mf*2048 + ks*32;
            ldmx4(AH[mf], wbase + sw128(o));
            ldmx4(AL[mf], wbase + sw128(o + 64));
        }
#pragma unroll
        for (int nb = 0; nb < 2; nb++) {
            unsigned o = (bRowB + wn*32 + nb*16)*128 + bKH + ks*32;
            ldmx4(BH[nb], pbase + sw128(o));
            ldmx4(BL[nb], pbase + sw128(o + 64));
        }
#pragma unroll
        for (int mf = 0; mf < 4; mf++)
#pragma unroll
            for (int nb = 0; nb < 2; nb++)
#pragma unroll
                for (int ns = 0; ns < 2; ns++) {
                    float* c = acc[mf][nb*2 + ns];
                    mma_bf16(c, AH[mf], BH[nb][ns*2], BH[nb][ns*2+1]);
                    mma_bf16(c, AH[mf], BL[nb][ns*2], BL[nb][ns*2+1]);
                    mma_bf16(c, AL[mf], BH[nb][ns*2], BH[nb][ns*2+1]);
                }
    };

    loadPJ(0, 0); loadP(0, 0); cp_commit();
    cp_wait0(); __syncthreads();
    genW(0); __syncthreads();

    for (int c = 0; c < 64; c++) {
        const int cur = c & 1, nxt = cur ^ 1;
        if (c < 63) { loadPJ(c+1, nxt); loadP(c+1, nxt); }
        cp_commit();
        mma_step(cur, 0);
        if (c < 63) {
            cp_wait0(); __syncthreads();
            genW(nxt);
        }
        mma_step(cur, 1);
        __syncthreads();
    }

    // ---- epilogue: write bf16 hi/lo split of field ---------------------------
#pragma unroll
    for (int mf = 0; mf < 4; mf++)
#pragma unroll
        for (int nf = 0; nf < 4; nf++) {
            const float* cc = acc[mf][nf];
            int i = i0 + wm*64 + mf*16 + (l >> 2);
            int d = d0 + wn*32 + nf*8 + (l & 3)*2;
            size_t o1 = ((size_t)bk*NQ + i)*DQ + d;
            size_t o2 = o1 + (size_t)8*DQ;
            __nv_bfloat162 h2, l2;
            h2.x = __float2bfloat16(cc[0]); h2.y = __float2bfloat16(cc[1]);
            l2.x = __float2bfloat16(cc[0] - __bfloat162float(h2.x));
            l2.y = __float2bfloat16(cc[1] - __bfloat162float(h2.y));
            *(__nv_bfloat162*)(g_fh + o1) = h2;
            *(__nv_bfloat162*)(g_fl + o1) = l2;
            h2.x = __float2bfloat16(cc[2]); h2.y = __float2bfloat16(cc[3]);
            l2.x = __float2bfloat16(cc[2] - __bfloat162float(h2.x));
            l2.y = __float2bfloat16(cc[3] - __bfloat162float(h2.y));
            *(__nv_bfloat162*)(g_fh + o2) = h2;
            *(__nv_bfloat162*)(g_fl + o2) = l2;
        }
}

// ---------------------------------------------------------------------------
// Kernel C v2 (mma.sync bf16 + LN): out[b,i,:] = LN(field_row @ Wcb^T)*gamma+beta
// Block: 32 i-rows x full 512 dout. 256 thr, 8 warps (each owns 64 dout).
// K=2048 in 128 chunks of 16, double-buffered cp.async. 3-way bf16 split.
// ---------------------------------------------------------------------------
__global__ __launch_bounds__(256, 1) void combine_mma_kernel(
    const float* __restrict__ gammaP, const float* __restrict__ betaP,
    float* __restrict__ out)
{
    extern __shared__ char smc[];
    const unsigned sb = smem_u32(smc);
    const int t = threadIdx.x, l = t & 31, w = t >> 5;
    const int i0 = blockIdx.x * 32;
    const int b  = blockIdx.y;

    float* rowSum = (float*)(smc + CM_LN);
    float* rowSq  = rowSum + 1024;
    float* gammaS = (float*)(smc + CM_GB);
    float* betaS  = gammaS + 512;
    __shared__ float meanS[32], rsS[32];

    for (int u = t; u < 512; u += 256) { gammaS[u] = gammaP[u]; betaS[u] = betaP[u]; }

    float acc[2][8][4];
#pragma unroll
    for (int mf = 0; mf < 2; mf++)
#pragma unroll
        for (int nf = 0; nf < 8; nf++)
#pragma unroll
            for (int q = 0; q < 4; q++) acc[mf][nf][q] = 0.0f;

    // ---- loaders: chunk c covers kd [c*16, c*16+16) -> k=c>>5, d0=(c&31)*16
    auto loadA = [&](int c, int buf) {
        if (t < 128) {
            int row = t >> 2, s = t & 3, sel = s >> 1, h = s & 1;
            int k = c >> 5, d0 = (c & 31)*16;
            const __nv_bfloat16* src = (sel ? g_fl : g_fh) +
                ((size_t)(b*KQ + k)*NQ + i0 + row)*DQ + d0 + h*8;
            cp16(sb + CM_A + buf*2048 + sw64row(row, sel*32 + h*16), src);
        }
    };
    auto loadB = [&](int c, int buf) {
        unsigned dst = sb + CM_B + buf*32768;
#pragma unroll
        for (int rr = 0; rr < 2; rr++) {
            int row = t*2 + rr;
            const __nv_bfloat16* srcH = g_cbh + (size_t)row*KDQ + c*16;
            const __nv_bfloat16* srcL = g_cbl + (size_t)row*KDQ + c*16;
            cp16(dst + sw64row(row, 0),  srcH);
            cp16(dst + sw64row(row, 16), srcH + 8);
            cp16(dst + sw64row(row, 32), srcL);
            cp16(dst + sw64row(row, 48), srcL + 8);
        }
    };

    // ldmatrix lane bases
    const unsigned aRow = (unsigned)(l & 15);
    const unsigned aH   = (unsigned)((l >> 4)*16);
    const unsigned bRow = (unsigned)((l & 7) + ((l >> 4) & 1)*8);
    const unsigned bH   = (unsigned)(((l >> 3) & 1)*16);

    loadA(0, 0); loadB(0, 0); cp_commit();
    cp_wait0(); __syncthreads();

    for (int c = 0; c < 128; c++) {
        const int cur = c & 1, nxt = cur ^ 1;
        if (c + 1 < 128) { loadA(c+1, nxt); loadB(c+1, nxt); }
        cp_commit();

        const unsigned abase = sb + CM_A + cur*2048;
        const unsigned bbase = sb + CM_B + cur*32768;
        uint32_t AH[2][4], AL[2][4], BH[4][4], BL[4][4];
#pragma unroll
        for (int mf = 0; mf < 2; mf++) {
            unsigned r = mf*16 + aRow;
            ldmx4(AH[mf], abase + sw64row(r, aH));
            ldmx4(AL[mf], abase + sw64row(r, 32 + aH));
        }
#pragma unroll
        for (int nb = 0; nb < 4; nb++) {
            unsigned r = w*64 + nb*16 + bRow;
            ldmx4(BH[nb], bbase + sw64row(r, bH));
            ldmx4(BL[nb], bbase + sw64row(r, 32 + bH));
        }
#pragma unroll
        for (int mf = 0; mf < 2; mf++)
#pragma unroll
            for (int nb = 0; nb < 4; nb++)
#pragma unroll
                for (int ns = 0; ns < 2; ns++) {
                    float* cc = acc[mf][nb*2 + ns];
                    mma_bf16(cc, AH[mf], BH[nb][ns*2], BH[nb][ns*2+1]);
                    mma_bf16(cc, AH[mf], BL[nb][ns*2], BL[nb][ns*2+1]);
                    mma_bf16(cc, AL[mf], BH[nb][ns*2], BH[nb][ns*2+1]);
                }

        if (c + 1 < 128) { cp_wait0(); }
        __syncthreads();
    }

    // ---- LayerNorm ----
    const int cw = w*4 + (l & 3);
#pragma unroll
    for (int mf = 0; mf < 2; mf++) {
        float sLo = 0.f, sHi = 0.f, qLo = 0.f, qHi = 0.f;
#pragma unroll
        for (int nf = 0; nf < 8; nf++) {
            const float* cc = acc[mf][nf];
            sLo += cc[0] + cc[1];  qLo += cc[0]*cc[0] + cc[1]*cc[1];
            sHi += cc[2] + cc[3];  qHi += cc[2]*cc[2] + cc[3]*cc[3];
        }
        int rLo = mf*16 + (l >> 2), rHi = rLo + 8;
        rowSum[rLo*32 + cw] = sLo;  rowSq[rLo*32 + cw] = qLo;
        rowSum[rHi*32 + cw] = sHi;  rowSq[rHi*32 + cw] = qHi;
    }
    __syncthreads();
#pragma unroll
    for (int rr = 0; rr < 4; rr++) {
        int row = w*4 + rr;
        float s  = rowSum[row*32 + l];
        float s2 = rowSq [row*32 + l];
#pragma unroll
        for (int off = 16; off > 0; off >>= 1) {
            s  += __shfl_xor_sync(0xffffffffu, s,  off);
            s2 += __shfl_xor_sync(0xffffffffu, s2, off);
        }
        if (l == 0) {
            float mean = s * (1.0f/512.0f);
            float var  = s2 * (1.0f/512.0f) - mean*mean;
            meanS[row] = mean;
            rsS[row]   = rsqrtf(var + 1e-5f);
        }
    }
    __syncthreads();

#pragma unroll
    for (int mf = 0; mf < 2; mf++)
#pragma unroll
        for (int nf = 0; nf < 8; nf++) {
            const float* cc = acc[mf][nf];
            int dout = w*64 + nf*8 + (l & 3)*2;
            float g0 = gammaS[dout], g1 = gammaS[dout+1];
            float b0 = betaS[dout],  b1 = betaS[dout+1];
            int rLo = mf*16 + (l >> 2), rHi = rLo + 8;
            float mLo = meanS[rLo], rsLo = rsS[rLo];
            float mHi = meanS[rHi], rsHi = rsS[rHi];
            float* dLo = out + ((size_t)b*NQ + i0 + rLo)*DQ + dout;
            float* dHi = out + ((size_t)b*NQ + i0 + rHi)*DQ + dout;
            *(float2*)dLo = make_float2((cc[0]-mLo)*rsLo*g0 + b0,
                                        (cc[1]-mLo)*rsLo*g1 + b1);
            *(float2*)dHi = make_float2((cc[2]-mHi)*rsHi*g0 + b0,
                                        (cc[3]-mHi)*rsHi*g1 + b1);
        }
}

// ---------------------------------------------------------------------------
extern "C" void kernel_launch(void* const* d_in, const int* in_sizes, int n_in,
                              void* d_out, int out_size)
{
    const float* charge   = (const float*)d_in[0];
    const float* position = (const float*)d_in[1];
    const float* mass     = (const float*)d_in[2];
    const float* lbw      = (const float*)d_in[3];
    const float* Wch      = (const float*)d_in[4];
    const float* Wcb      = (const float*)d_in[5];
    const float* gammaP   = (const float*)d_in[6];
    const float* betaP    = (const float*)d_in[7];
    float* out = (float*)d_out;

    cudaFuncSetAttribute(field_mma_kernel,
                         cudaFuncAttributeMaxDynamicSharedMemorySize, SMEM_FIELD);
    cudaFuncSetAttribute(combine_mma_kernel,
                         cudaFuncAttributeMaxDynamicSharedMemorySize, SMEM_COMB);

    proj_gemm_kernel <<<dim3(NQ/128, KDQ/128, BQ), 256>>>(charge, Wch);
    split_t_kernel   <<<dim3(NQ/32, DQ/32, BQ*KQ), 256>>>(mass);
    split_cb_kernel  <<<(DQ*KDQ)/1024, 256>>>(Wcb);
    field_mma_kernel <<<dim3(NQ/128, DQ/128, BQ*KQ), 256, SMEM_FIELD>>>(position, lbw);
    combine_mma_kernel<<<dim3(NQ/32, BQ), 256, SMEM_COMB>>>(gammaP, betaP, out);
}

// round 7
// speedup vs baseline: 1.9177x; 1.1675x over previous
#include <cuda_runtime.h>
#include <cuda_bf16.h>
#include <cstdint>

// Problem constants
#define BQ 4
#define NQ 2048
#define DQ 512
#define PQ 16
#define KQ 4
#define KDQ (KQ*DQ)

// Scratch
__device__ float g_proj [BQ*KQ*NQ*DQ];
__device__ __nv_bfloat16 g_pT_hi[(size_t)BQ*KQ*DQ*NQ];   // [bk][d][j]  (mass folded in)
__device__ __nv_bfloat16 g_pT_lo[(size_t)BQ*KQ*DQ*NQ];
__device__ __nv_bfloat16 g_fh[(size_t)BQ*KQ*NQ*DQ];      // field bf16 hi  [bk][i][d]
__device__ __nv_bfloat16 g_fl[(size_t)BQ*KQ*NQ*DQ];      // field bf16 lo
__device__ __nv_bfloat16 g_cbh[(size_t)DQ*KDQ];          // W_combine hi [dout][kd]
__device__ __nv_bfloat16 g_cbl[(size_t)DQ*KDQ];          // W_combine lo
__device__ __nv_bfloat16 g_wh[(size_t)BQ*KQ*NQ*NQ];      // weights hi [bk][i][j]
__device__ __nv_bfloat16 g_wl[(size_t)BQ*KQ*NQ*NQ];      // weights lo

// ---------------------------------------------------------------------------
// helpers (portable PTX only: cp.async / ldmatrix / mma.sync — sm_80+ baseline)
// ---------------------------------------------------------------------------
__device__ __forceinline__ unsigned smem_u32(const void* p) {
    return (unsigned)__cvta_generic_to_shared(p);
}
__device__ __forceinline__ void cp16(unsigned dst, const void* src) {
    asm volatile("cp.async.cg.shared.global [%0], [%1], 16;" :: "r"(dst), "l"(src));
}
__device__ __forceinline__ void cp_commit() { asm volatile("cp.async.commit_group;"); }
__device__ __forceinline__ void cp_wait0()  { asm volatile("cp.async.wait_group 0;"); }

__device__ __forceinline__ unsigned sw128(unsigned o) {   // SW128: bits[6:4] ^= bits[9:7]
    return o ^ ((o >> 3) & 0x70u);
}
__device__ __forceinline__ unsigned sw64row(unsigned row, unsigned seg) {
    return row*64u + (seg ^ ((row & 6u) << 3));
}

__device__ __forceinline__ void ldmx4(uint32_t* r, unsigned addr) {
    asm volatile("ldmatrix.sync.aligned.m8n8.x4.shared.b16 {%0,%1,%2,%3}, [%4];"
                 : "=r"(r[0]), "=r"(r[1]), "=r"(r[2]), "=r"(r[3]) : "r"(addr));
}

__device__ __forceinline__ void mma_bf16(float* c, const uint32_t* a,
                                         uint32_t b0, uint32_t b1) {
    asm volatile("mma.sync.aligned.m16n8k16.row.col.f32.bf16.bf16.f32 "
                 "{%0,%1,%2,%3}, {%4,%5,%6,%7}, {%8,%9}, {%0,%1,%2,%3};"
                 : "+f"(c[0]), "+f"(c[1]), "+f"(c[2]), "+f"(c[3])
                 : "r"(a[0]), "r"(a[1]), "r"(a[2]), "r"(a[3]), "r"(b0), "r"(b1));
}

// field GEMM smem: A 2x16KB | B 2x16KB
#define FG_A   0
#define FG_B   32768
#define SMEM_FG 65536

// combine kernel smem layout
#define CM_A   0          // 2 x 2KB
#define CM_B   4096       // 2 x 32KB
#define CM_LN  69632      // rowSum 4KB | rowSq 4KB
#define CM_GB  77824      // gamma 2KB | beta 2KB
#define SMEM_COMB 81920

// ---------------------------------------------------------------------------
// Kernel A: projection GEMM (unchanged, passing @405us)
// ---------------------------------------------------------------------------
__global__ __launch_bounds__(256) void proj_gemm_kernel(
    const float* __restrict__ charge, const float* __restrict__ Wch)
{
    const int b  = blockIdx.z;
    const int j0 = blockIdx.x * 128;
    const int n0 = blockIdx.y * 128;
    const int t  = threadIdx.x;
    const int tx = t & 15, ty = t >> 4;

    __shared__ float As[8][128];
    __shared__ float Bs[8][128];

    float acc[8][8];
#pragma unroll
    for (int r = 0; r < 8; r++)
#pragma unroll
        for (int q = 0; q < 8; q++) acc[r][q] = 0.0f;

    const float* Abase = charge + (b*NQ + j0)*DQ;

    for (int c0 = 0; c0 < DQ; c0 += 8) {
        {
            int jj = t >> 1, cgp = t & 1;
            float4 v = *(const float4*)(Abase + jj*DQ + c0 + cgp*4);
            As[cgp*4+0][jj] = v.x; As[cgp*4+1][jj] = v.y;
            As[cgp*4+2][jj] = v.z; As[cgp*4+3][jj] = v.w;
        }
        {
            int kdj = t & 127, cgp = t >> 7;
            float4 v = *(const float4*)(Wch + (n0+kdj)*DQ + c0 + cgp*4);
            Bs[cgp*4+0][kdj] = v.x; Bs[cgp*4+1][kdj] = v.y;
            Bs[cgp*4+2][kdj] = v.z; Bs[cgp*4+3][kdj] = v.w;
        }
        __syncthreads();
#pragma unroll
        for (int kk = 0; kk < 8; kk++) {
            float a[8], bb[8];
            *(float4*)&a[0]  = *(const float4*)&As[kk][ty*8];
            *(float4*)&a[4]  = *(const float4*)&As[kk][ty*8+4];
            *(float4*)&bb[0] = *(const float4*)&Bs[kk][tx*4];
            *(float4*)&bb[4] = *(const float4*)&Bs[kk][64 + tx*4];
#pragma unroll
            for (int r = 0; r < 8; r++)
#pragma unroll
                for (int q = 0; q < 8; q++)
                    acc[r][q] += a[r]*bb[q];
        }
        __syncthreads();
    }

    const int c1 = n0 + tx*4;
    const int c2 = c1 + 64;
    const int k1 = c1 >> 9, d1 = c1 & 511;
    const int k2 = c2 >> 9, d2 = c2 & 511;
#pragma unroll
    for (int r = 0; r < 8; r++) {
        int j = j0 + ty*8 + r;
        *(float4*)(g_proj + ((b*KQ + k1)*NQ + j)*DQ + d1) =
            make_float4(acc[r][0], acc[r][1], acc[r][2], acc[r][3]);
        *(float4*)(g_proj + ((b*KQ + k2)*NQ + j)*DQ + d2) =
            make_float4(acc[r][4], acc[r][5], acc[r][6], acc[r][7]);
    }
}

// ---------------------------------------------------------------------------
// Kernel A2: transpose + mass-scale + bf16 hi/lo split of proj
// ---------------------------------------------------------------------------
__global__ __launch_bounds__(256) void split_t_kernel(const float* __restrict__ mass)
{
    __shared__ float tile[32][33];
    const int bk = blockIdx.z;
    const int j0 = blockIdx.x * 32, d0 = blockIdx.y * 32;
    const int tx = threadIdx.x & 31, ty = threadIdx.x >> 5;
    const float* src = g_proj + ((size_t)bk*NQ + j0)*DQ + d0;
#pragma unroll
    for (int r = 0; r < 4; r++)
        tile[r*8+ty][tx] = src[(size_t)(r*8+ty)*DQ + tx];
    __syncthreads();
    const int b = bk >> 2;
    const float mj = mass[(size_t)b*NQ + j0 + tx];
    const size_t ob = ((size_t)bk*DQ + d0)*NQ + j0;
#pragma unroll
    for (int r = 0; r < 4; r++) {
        int d = r*8 + ty;
        float v = tile[tx][d] * mj;
        __nv_bfloat16 h = __float2bfloat16(v);
        __nv_bfloat16 l = __float2bfloat16(v - __bfloat162float(h));
        g_pT_hi[ob + (size_t)d*NQ + tx] = h;
        g_pT_lo[ob + (size_t)d*NQ + tx] = l;
    }
}

// ---------------------------------------------------------------------------
// Kernel A3: bf16 hi/lo split of W_combine
// ---------------------------------------------------------------------------
__global__ __launch_bounds__(256) void split_cb_kernel(const float* __restrict__ Wcb)
{
    const size_t idx = (size_t)blockIdx.x*1024 + threadIdx.x*4;
    float4 v = *(const float4*)(Wcb + idx);
    float vv[4] = {v.x, v.y, v.z, v.w};
#pragma unroll
    for (int q = 0; q < 4; q++) {
        __nv_bfloat16 h = __float2bfloat16(vv[q]);
        g_cbh[idx + q] = h;
        g_cbl[idx + q] = __float2bfloat16(vv[q] - __bfloat162float(h));
    }
}

// ---------------------------------------------------------------------------
// Kernel W: weight generation.  g_w{h,l}[b,k,i,j] = split(exp(-d2(b,i,j)*c_k))
// d2 computed ONCE per (b,i,j); exp computed once per distinct bandwidth
// (all-equal bandwidths -> 1 exp per pair instead of 4).
// Block: (j-tile 128, i-tile 128, b). Thread owns 2 consecutive j, loops 32 i.
// ---------------------------------------------------------------------------
__global__ __launch_bounds__(256) void wgen_kernel(
    const float* __restrict__ position, const float* __restrict__ lbw)
{
    __shared__ float posI[128*16];
    const int b = blockIdx.z, i0 = blockIdx.y*128, j0 = blockIdx.x*128;
    const int t = threadIdx.x;

    for (int u = t; u < 512; u += 256) {
        int r = u >> 2, q = u & 3;
        *(float4*)&posI[r*16 + q*4] =
            *(const float4*)(position + ((size_t)b*NQ + i0 + r)*PQ + q*4);
    }

    float negc[4];
#pragma unroll
    for (int k = 0; k < 4; k++) negc[k] = -1.0f/(2.0f*__expf(lbw[k]) + 1e-8f);
    const bool eq[4] = {false, negc[1] == negc[0], negc[2] == negc[0], negc[3] == negc[0]};

    const int jp = (t & 63)*2;      // local j (2 consecutive)
    const int ig = t >> 6;          // 0..3 -> i sub-range of 32

    float pj[32];
#pragma unroll
    for (int u2 = 0; u2 < 2; u2++) {
        const float* p = position + ((size_t)b*NQ + j0 + jp + u2)*PQ;
#pragma unroll
        for (int q = 0; q < 16; q += 4) {
            float4 v = *(const float4*)(p + q);
            pj[u2*16+q] = v.x; pj[u2*16+q+1] = v.y;
            pj[u2*16+q+2] = v.z; pj[u2*16+q+3] = v.w;
        }
    }
    __syncthreads();

    for (int ii = 0; ii < 32; ii++) {
        const int i = ig*32 + ii;
        const float* pi = &posI[i*16];
        float d2a = 0.f, d2b = 0.f;
#pragma unroll
        for (int q = 0; q < 16; q++) {
            float piq = pi[q];
            float da = piq - pj[q], db = piq - pj[16+q];
            d2a = fmaf(da, da, d2a); d2b = fmaf(db, db, d2b);
        }
        float ea[4], eb[4];
        ea[0] = __expf(d2a*negc[0]);
        eb[0] = __expf(d2b*negc[0]);
#pragma unroll
        for (int k = 1; k < 4; k++) {
            ea[k] = eq[k] ? ea[0] : __expf(d2a*negc[k]);
            eb[k] = eq[k] ? eb[0] : __expf(d2b*negc[k]);
        }
#pragma unroll
        for (int k = 0; k < 4; k++) {
            __nv_bfloat162 h2, l2;
            h2.x = __float2bfloat16(ea[k]);
            h2.y = __float2bfloat16(eb[k]);
            l2.x = __float2bfloat16(ea[k] - __bfloat162float(h2.x));
            l2.y = __float2bfloat16(eb[k] - __bfloat162float(h2.y));
            size_t off = ((size_t)(b*KQ + k)*NQ + i0 + i)*NQ + j0 + jp;
            *(__nv_bfloat162*)(g_wh + off) = h2;
            *(__nv_bfloat162*)(g_wl + off) = l2;
        }
    }
}

// ---------------------------------------------------------------------------
// Kernel B v5: pure bf16 GEMM.  field[bk,i,d] = sum_j W[bk,i,j] * pT[bk,d,j]
// Block 128(i) x 128(d), K=2048 in 64 chunks of 32, double-buffered cp.async.
// 3-way bf16 split. Writes field bf16 hi/lo. No exp, no genW in loop.
// ---------------------------------------------------------------------------
__global__ __launch_bounds__(256, 1) void field_gemm_kernel()
{
    extern __shared__ char smc[];
    const unsigned sb = smem_u32(smc);
    const int t = threadIdx.x, l = t & 31, w = t >> 5;
    const int wm = w & 1, wn = w >> 1;
    const int i0 = blockIdx.x * 128, d0 = blockIdx.y * 128;
    const int bk = blockIdx.z;

    const unsigned aOffB = (unsigned)((wm*64 + (l & 15))*128 + (l >> 4)*16);
    const unsigned bRowB = (unsigned)((l & 7) + ((l >> 4) & 1)*8);
    const unsigned bKH   = (unsigned)(((l >> 3) & 1)*16);

    float acc[4][4][4];
#pragma unroll
    for (int a = 0; a < 4; a++)
#pragma unroll
        for (int n = 0; n < 4; n++)
#pragma unroll
            for (int q = 0; q < 4; q++) acc[a][n][q] = 0.0f;

    auto loadA = [&](int c, int buf) {     // W tile: 128 i-rows x [hi 64B | lo 64B]
        int row = t >> 1, sel = t & 1;
        const __nv_bfloat16* src = (sel ? g_wl : g_wh) +
            ((size_t)bk*NQ + i0 + row)*NQ + c*32;
        unsigned dst = sb + FG_A + buf*16384;
        unsigned base = (unsigned)(row*128 + sel*64);
#pragma unroll
        for (int cc = 0; cc < 4; cc++)
            cp16(dst + sw128(base + cc*16), (const char*)src + cc*16);
    };
    auto loadB = [&](int c, int buf) {     // P tile: 128 d-rows x [hi 64B | lo 64B]
        int row = t >> 1, sel = t & 1;
        const __nv_bfloat16* src = (sel ? g_pT_lo : g_pT_hi) +
            ((size_t)bk*DQ + d0 + row)*NQ + c*32;
        unsigned dst = sb + FG_B + buf*16384;
        unsigned base = (unsigned)(row*128 + sel*64);
#pragma unroll
        for (int cc = 0; cc < 4; cc++)
            cp16(dst + sw128(base + cc*16), (const char*)src + cc*16);
    };

    auto mma_step = [&](int buf, int ks) {
        const unsigned abase = sb + FG_A + buf*16384;
        const unsigned pbase = sb + FG_B + buf*16384;
        uint32_t AH[4][4], AL[4][4], BH[2][4], BL[2][4];
#pragma unroll
        for (int mf = 0; mf < 4; mf++) {
            unsigned o = aOffB + mf*2048 + ks*32;
            ldmx4(AH[mf], abase + sw128(o));
            ldmx4(AL[mf], abase + sw128(o + 64));
        }
#pragma unroll
        for (int nb = 0; nb < 2; nb++) {
            unsigned o = (bRowB + wn*32 + nb*16)*128 + bKH + ks*32;
            ldmx4(BH[nb], pbase + sw128(o));
            ldmx4(BL[nb], pbase + sw128(o + 64));
        }
#pragma unroll
        for (int mf = 0; mf < 4; mf++)
#pragma unroll
            for (int nb = 0; nb < 2; nb++)
#pragma unroll
                for (int ns = 0; ns < 2; ns++) {
                    float* c = acc[mf][nb*2 + ns];
                    mma_bf16(c, AH[mf], BH[nb][ns*2], BH[nb][ns*2+1]);
                    mma_bf16(c, AH[mf], BL[nb][ns*2], BL[nb][ns*2+1]);
                    mma_bf16(c, AL[mf], BH[nb][ns*2], BH[nb][ns*2+1]);
                }
    };

    loadA(0, 0); loadB(0, 0); cp_commit();
    cp_wait0(); __syncthreads();

    for (int c = 0; c < 64; c++) {
        const int cur = c & 1, nxt = cur ^ 1;
        if (c < 63) { loadA(c+1, nxt); loadB(c+1, nxt); cp_commit(); }
        mma_step(cur, 0);
        mma_step(cur, 1);
        if (c < 63) { cp_wait0(); }
        __syncthreads();
    }

    // epilogue: write bf16 hi/lo split of field
#pragma unroll
    for (int mf = 0; mf < 4; mf++)
#pragma unroll
        for (int nf = 0; nf < 4; nf++) {
            const float* cc = acc[mf][nf];
            int i = i0 + wm*64 + mf*16 + (l >> 2);
            int d = d0 + wn*32 + nf*8 + (l & 3)*2;
            size_t o1 = ((size_t)bk*NQ + i)*DQ + d;
            size_t o2 = o1 + (size_t)8*DQ;
            __nv_bfloat162 h2, l2;
            h2.x = __float2bfloat16(cc[0]); h2.y = __float2bfloat16(cc[1]);
            l2.x = __float2bfloat16(cc[0] - __bfloat162float(h2.x));
            l2.y = __float2bfloat16(cc[1] - __bfloat162float(h2.y));
            *(__nv_bfloat162*)(g_fh + o1) = h2;
            *(__nv_bfloat162*)(g_fl + o1) = l2;
            h2.x = __float2bfloat16(cc[2]); h2.y = __float2bfloat16(cc[3]);
            l2.x = __float2bfloat16(cc[2] - __bfloat162float(h2.x));
            l2.y = __float2bfloat16(cc[3] - __bfloat162float(h2.y));
            *(__nv_bfloat162*)(g_fh + o2) = h2;
            *(__nv_bfloat162*)(g_fl + o2) = l2;
        }
}

// ---------------------------------------------------------------------------
// Kernel C (mma.sync bf16 + LN): unchanged from R5 (passing)
// ---------------------------------------------------------------------------
__global__ __launch_bounds__(256, 1) void combine_mma_kernel(
    const float* __restrict__ gammaP, const float* __restrict__ betaP,
    float* __restrict__ out)
{
    extern __shared__ char smc[];
    const unsigned sb = smem_u32(smc);
    const int t = threadIdx.x, l = t & 31, w = t >> 5;
    const int i0 = blockIdx.x * 32;
    const int b  = blockIdx.y;

    float* rowSum = (float*)(smc + CM_LN);
    float* rowSq  = rowSum + 1024;
    float* gammaS = (float*)(smc + CM_GB);
    float* betaS  = gammaS + 512;
    __shared__ float meanS[32], rsS[32];

    for (int u = t; u < 512; u += 256) { gammaS[u] = gammaP[u]; betaS[u] = betaP[u]; }

    float acc[2][8][4];
#pragma unroll
    for (int mf = 0; mf < 2; mf++)
#pragma unroll
        for (int nf = 0; nf < 8; nf++)
#pragma unroll
            for (int q = 0; q < 4; q++) acc[mf][nf][q] = 0.0f;

    auto loadA = [&](int c, int buf) {
        if (t < 128) {
            int row = t >> 2, s = t & 3, sel = s >> 1, h = s & 1;
            int k = c >> 5, d0 = (c & 31)*16;
            const __nv_bfloat16* src = (sel ? g_fl : g_fh) +
                ((size_t)(b*KQ + k)*NQ + i0 + row)*DQ + d0 + h*8;
            cp16(sb + CM_A + buf*2048 + sw64row(row, sel*32 + h*16), src);
        }
    };
    auto loadB = [&](int c, int buf) {
        unsigned dst = sb + CM_B + buf*32768;
#pragma unroll
        for (int rr = 0; rr < 2; rr++) {
            int row = t*2 + rr;
            const __nv_bfloat16* srcH = g_cbh + (size_t)row*KDQ + c*16;
            const __nv_bfloat16* srcL = g_cbl + (size_t)row*KDQ + c*16;
            cp16(dst + sw64row(row, 0),  srcH);
            cp16(dst + sw64row(row, 16), srcH + 8);
            cp16(dst + sw64row(row, 32), srcL);
            cp16(dst + sw64row(row, 48), srcL + 8);
        }
    };

    const unsigned aRow = (unsigned)(l & 15);
    const unsigned aH   = (unsigned)((l >> 4)*16);
    const unsigned bRow = (unsigned)((l & 7) + ((l >> 4) & 1)*8);
    const unsigned bH   = (unsigned)(((l >> 3) & 1)*16);

    loadA(0, 0); loadB(0, 0); cp_commit();
    cp_wait0(); __syncthreads();

    for (int c = 0; c < 128; c++) {
        const int cur = c & 1, nxt = cur ^ 1;
        if (c + 1 < 128) { loadA(c+1, nxt); loadB(c+1, nxt); }
        cp_commit();

        const unsigned abase = sb + CM_A + cur*2048;
        const unsigned bbase = sb + CM_B + cur*32768;
        uint32_t AH[2][4], AL[2][4], BH[4][4], BL[4][4];
#pragma unroll
        for (int mf = 0; mf < 2; mf++) {
            unsigned r = mf*16 + aRow;
            ldmx4(AH[mf], abase + sw64row(r, aH));
            ldmx4(AL[mf], abase + sw64row(r, 32 + aH));
        }
#pragma unroll
        for (int nb = 0; nb < 4; nb++) {
            unsigned r = w*64 + nb*16 + bRow;
            ldmx4(BH[nb], bbase + sw64row(r, bH));
            ldmx4(BL[nb], bbase + sw64row(r, 32 + bH));
        }
#pragma unroll
        for (int mf = 0; mf < 2; mf++)
#pragma unroll
            for (int nb = 0; nb < 4; nb++)
#pragma unroll
                for (int ns = 0; ns < 2; ns++) {
                    float* cc = acc[mf][nb*2 + ns];
                    mma_bf16(cc, AH[mf], BH[nb][ns*2], BH[nb][ns*2+1]);
                    mma_bf16(cc, AH[mf], BL[nb][ns*2], BL[nb][ns*2+1]);
                    mma_bf16(cc, AL[mf], BH[nb][ns*2], BH[nb][ns*2+1]);
                }

        if (c + 1 < 128) { cp_wait0(); }
        __syncthreads();
    }

    const int cw = w*4 + (l & 3);
#pragma unroll
    for (int mf = 0; mf < 2; mf++) {
        float sLo = 0.f, sHi = 0.f, qLo = 0.f, qHi = 0.f;
#pragma unroll
        for (int nf = 0; nf < 8; nf++) {
            const float* cc = acc[mf][nf];
            sLo += cc[0] + cc[1];  qLo += cc[0]*cc[0] + cc[1]*cc[1];
            sHi += cc[2] + cc[3];  qHi += cc[2]*cc[2] + cc[3]*cc[3];
        }
        int rLo = mf*16 + (l >> 2), rHi = rLo + 8;
        rowSum[rLo*32 + cw] = sLo;  rowSq[rLo*32 + cw] = qLo;
        rowSum[rHi*32 + cw] = sHi;  rowSq[rHi*32 + cw] = qHi;
    }
    __syncthreads();
#pragma unroll
    for (int rr = 0; rr < 4; rr++) {
        int row = w*4 + rr;
        float s  = rowSum[row*32 + l];
        float s2 = rowSq [row*32 + l];
#pragma unroll
        for (int off = 16; off > 0; off >>= 1) {
            s  += __shfl_xor_sync(0xffffffffu, s,  off);
            s2 += __shfl_xor_sync(0xffffffffu, s2, off);
        }
        if (l == 0) {
            float mean = s * (1.0f/512.0f);
            float var  = s2 * (1.0f/512.0f) - mean*mean;
            meanS[row] = mean;
            rsS[row]   = rsqrtf(var + 1e-5f);
        }
    }
    __syncthreads();

#pragma unroll
    for (int mf = 0; mf < 2; mf++)
#pragma unroll
        for (int nf = 0; nf < 8; nf++) {
            const float* cc = acc[mf][nf];
            int dout = w*64 + nf*8 + (l & 3)*2;
            float g0 = gammaS[dout], g1 = gammaS[dout+1];
            float b0 = betaS[dout],  b1 = betaS[dout+1];
            int rLo = mf*16 + (l >> 2), rHi = rLo + 8;
            float mLo = meanS[rLo], rsLo = rsS[rLo];
            float mHi = meanS[rHi], rsHi = rsS[rHi];
            float* dLo = out + ((size_t)b*NQ + i0 + rLo)*DQ + dout;
            float* dHi = out + ((size_t)b*NQ + i0 + rHi)*DQ + dout;
            *(float2*)dLo = make_float2((cc[0]-mLo)*rsLo*g0 + b0,
                                        (cc[1]-mLo)*rsLo*g1 + b1);
            *(float2*)dHi = make_float2((cc[2]-mHi)*rsHi*g0 + b0,
                                        (cc[3]-mHi)*rsHi*g1 + b1);
        }
}

// ---------------------------------------------------------------------------
extern "C" void kernel_launch(void* const* d_in, const int* in_sizes, int n_in,
                              void* d_out, int out_size)
{
    const float* charge   = (const float*)d_in[0];
    const float* position = (const float*)d_in[1];
    const float* mass     = (const float*)d_in[2];
    const float* lbw      = (const float*)d_in[3];
    const float* Wch      = (const float*)d_in[4];
    const float* Wcb      = (const float*)d_in[5];
    const float* gammaP   = (const float*)d_in[6];
    const float* betaP    = (const float*)d_in[7];
    float* out = (float*)d_out;

    cudaFuncSetAttribute(field_gemm_kernel,
                         cudaFuncAttributeMaxDynamicSharedMemorySize, SMEM_FG);
    cudaFuncSetAttribute(combine_mma_kernel,
                         cudaFuncAttributeMaxDynamicSharedMemorySize, SMEM_COMB);

    proj_gemm_kernel <<<dim3(NQ/128, KDQ/128, BQ), 256>>>(charge, Wch);
    split_t_kernel   <<<dim3(NQ/32, DQ/32, BQ*KQ), 256>>>(mass);
    split_cb_kernel  <<<(DQ*KDQ)/1024, 256>>>(Wcb);
    wgen_kernel      <<<dim3(NQ/128, NQ/128, BQ), 256>>>(position, lbw);
    field_gemm_kernel<<<dim3(NQ/128, DQ/128, BQ*KQ), 256, SMEM_FG>>>();
    combine_mma_kernel<<<dim3(NQ/32, BQ), 256, SMEM_COMB>>>(gammaP, betaP, out);
}

// round 8
// speedup vs baseline: 2.3234x; 1.2116x over previous
#include <cuda_runtime.h>
#include <cuda_bf16.h>
#include <cstdint>

// Problem constants
#define BQ 4
#define NQ 2048
#define DQ 512
#define PQ 16
#define KQ 4
#define KDQ (KQ*DQ)

// Scratch
__device__ float g_proj [BQ*KQ*NQ*DQ];
__device__ __nv_bfloat16 g_pT_hi[(size_t)BQ*KQ*DQ*NQ];   // [bk][d][j]  (mass folded in)
__device__ __nv_bfloat16 g_pT_lo[(size_t)BQ*KQ*DQ*NQ];
__device__ __nv_bfloat16 g_fh[(size_t)BQ*KQ*NQ*DQ];      // field bf16 hi  [bk][i][d]
__device__ __nv_bfloat16 g_fl[(size_t)BQ*KQ*NQ*DQ];      // field bf16 lo
__device__ __nv_bfloat16 g_cbh[(size_t)DQ*KDQ];          // W_combine hi [dout][kd]
__device__ __nv_bfloat16 g_cbl[(size_t)DQ*KDQ];          // W_combine lo
__device__ __nv_bfloat16 g_wh[(size_t)BQ*KQ*NQ*NQ];      // weights hi [bk][i][j]
__device__ __nv_bfloat16 g_wl[(size_t)BQ*KQ*NQ*NQ];      // weights lo
__device__ __nv_bfloat16 g_chh[(size_t)BQ*NQ*DQ];        // charge hi [b][j][c]
__device__ __nv_bfloat16 g_chl[(size_t)BQ*NQ*DQ];
__device__ __nv_bfloat16 g_cwh[(size_t)KDQ*DQ];          // W_charge hi [kd][c]
__device__ __nv_bfloat16 g_cwl[(size_t)KDQ*DQ];

// ---------------------------------------------------------------------------
// helpers (portable PTX only: cp.async / ldmatrix / mma.sync — sm_80+ baseline)
// ---------------------------------------------------------------------------
__device__ __forceinline__ unsigned smem_u32(const void* p) {
    return (unsigned)__cvta_generic_to_shared(p);
}
__device__ __forceinline__ void cp16(unsigned dst, const void* src) {
    asm volatile("cp.async.cg.shared.global [%0], [%1], 16;" :: "r"(dst), "l"(src));
}
__device__ __forceinline__ void cp_commit() { asm volatile("cp.async.commit_group;"); }
__device__ __forceinline__ void cp_wait0()  { asm volatile("cp.async.wait_group 0;"); }

__device__ __forceinline__ unsigned sw128(unsigned o) {   // SW128: bits[6:4] ^= bits[9:7]
    return o ^ ((o >> 3) & 0x70u);
}
__device__ __forceinline__ unsigned sw64row(unsigned row, unsigned seg) {
    return row*64u + (seg ^ ((row & 6u) << 3));
}

__device__ __forceinline__ void ldmx4(uint32_t* r, unsigned addr) {
    asm volatile("ldmatrix.sync.aligned.m8n8.x4.shared.b16 {%0,%1,%2,%3}, [%4];"
                 : "=r"(r[0]), "=r"(r[1]), "=r"(r[2]), "=r"(r[3]) : "r"(addr));
}

__device__ __forceinline__ void mma_bf16(float* c, const uint32_t* a,
                                         uint32_t b0, uint32_t b1) {
    asm volatile("mma.sync.aligned.m16n8k16.row.col.f32.bf16.bf16.f32 "
                 "{%0,%1,%2,%3}, {%4,%5,%6,%7}, {%8,%9}, {%0,%1,%2,%3};"
                 : "+f"(c[0]), "+f"(c[1]), "+f"(c[2]), "+f"(c[3])
                 : "r"(a[0]), "r"(a[1]), "r"(a[2]), "r"(a[3]), "r"(b0), "r"(b1));
}

// 128x128 GEMM smem: A 2x16KB | B 2x16KB
#define FG_A   0
#define FG_B   32768
#define SMEM_FG 65536

// combine kernel smem layout (64-row i-tile)
#define CM_A   0          // 2 x 4KB
#define CM_B   8192       // 2 x 32KB
#define CM_LN  73728      // rowSum 8KB | rowSq 8KB
#define CM_GB  90112      // gamma 2KB | beta 2KB
#define SMEM_COMB 94208

// ---------------------------------------------------------------------------
// Elementwise bf16 hi/lo split kernels
// ---------------------------------------------------------------------------
__global__ __launch_bounds__(256) void split_ch_kernel(const float* __restrict__ src)
{
    const size_t idx = (size_t)blockIdx.x*1024 + threadIdx.x*4;
    float4 v = *(const float4*)(src + idx);
    float vv[4] = {v.x, v.y, v.z, v.w};
#pragma unroll
    for (int q = 0; q < 4; q++) {
        __nv_bfloat16 h = __float2bfloat16(vv[q]);
        g_chh[idx + q] = h;
        g_chl[idx + q] = __float2bfloat16(vv[q] - __bfloat162float(h));
    }
}
__global__ __launch_bounds__(256) void split_cw_kernel(const float* __restrict__ src)
{
    const size_t idx = (size_t)blockIdx.x*1024 + threadIdx.x*4;
    float4 v = *(const float4*)(src + idx);
    float vv[4] = {v.x, v.y, v.z, v.w};
#pragma unroll
    for (int q = 0; q < 4; q++) {
        __nv_bfloat16 h = __float2bfloat16(vv[q]);
        g_cwh[idx + q] = h;
        g_cwl[idx + q] = __float2bfloat16(vv[q] - __bfloat162float(h));
    }
}
__global__ __launch_bounds__(256) void split_cb_kernel(const float* __restrict__ Wcb)
{
    const size_t idx = (size_t)blockIdx.x*1024 + threadIdx.x*4;
    float4 v = *(const float4*)(Wcb + idx);
    float vv[4] = {v.x, v.y, v.z, v.w};
#pragma unroll
    for (int q = 0; q < 4; q++) {
        __nv_bfloat16 h = __float2bfloat16(vv[q]);
        g_cbh[idx + q] = h;
        g_cbl[idx + q] = __float2bfloat16(vv[q] - __bfloat162float(h));
    }
}

// ---------------------------------------------------------------------------
// Kernel A (tensor): proj[b,j,kd] = sum_c charge[b,j,c] * Wch[kd,c]
// 128(j) x 128(kd) tiles, K=512 in 16 chunks of 32, 3-way bf16 split.
// Epilogue writes fp32 g_proj[(b,k)][j][d] (tiles never cross k-boundary).
// ---------------------------------------------------------------------------
__global__ __launch_bounds__(256, 1) void proj_mma_kernel()
{
    extern __shared__ char smc[];
    const unsigned sb = smem_u32(smc);
    const int t = threadIdx.x, l = t & 31, w = t >> 5;
    const int wm = w & 1, wn = w >> 1;
    const int j0 = blockIdx.x * 128, n0 = blockIdx.y * 128;
    const int b = blockIdx.z;

    const unsigned aOffB = (unsigned)((wm*64 + (l & 15))*128 + (l >> 4)*16);
    const unsigned bRowB = (unsigned)((l & 7) + ((l >> 4) & 1)*8);
    const unsigned bKH   = (unsigned)(((l >> 3) & 1)*16);

    float acc[4][4][4];
#pragma unroll
    for (int a = 0; a < 4; a++)
#pragma unroll
        for (int n = 0; n < 4; n++)
#pragma unroll
            for (int q = 0; q < 4; q++) acc[a][n][q] = 0.0f;

    auto loadA = [&](int c, int buf) {
        int row = t >> 1, sel = t & 1;
        const __nv_bfloat16* src = (sel ? g_chl : g_chh) +
            ((size_t)b*NQ + j0 + row)*DQ + c*32;
        unsigned dst = sb + FG_A + buf*16384;
        unsigned base = (unsigned)(row*128 + sel*64);
#pragma unroll
        for (int cc = 0; cc < 4; cc++)
            cp16(dst + sw128(base + cc*16), (const char*)src + cc*16);
    };
    auto loadB = [&](int c, int buf) {
        int row = t >> 1, sel = t & 1;
        const __nv_bfloat16* src = (sel ? g_cwl : g_cwh) +
            (size_t)(n0 + row)*DQ + c*32;
        unsigned dst = sb + FG_B + buf*16384;
        unsigned base = (unsigned)(row*128 + sel*64);
#pragma unroll
        for (int cc = 0; cc < 4; cc++)
            cp16(dst + sw128(base + cc*16), (const char*)src + cc*16);
    };

    auto mma_step = [&](int buf, int ks) {
        const unsigned abase = sb + FG_A + buf*16384;
        const unsigned pbase = sb + FG_B + buf*16384;
        uint32_t AH[4][4], AL[4][4], BH[2][4], BL[2][4];
#pragma unroll
        for (int mf = 0; mf < 4; mf++) {
            unsigned o = aOffB + mf*2048 + ks*32;
            ldmx4(AH[mf], abase + sw128(o));
            ldmx4(AL[mf], abase + sw128(o + 64));
        }
#pragma unroll
        for (int nb = 0; nb < 2; nb++) {
            unsigned o = (bRowB + wn*32 + nb*16)*128 + bKH + ks*32;
            ldmx4(BH[nb], pbase + sw128(o));
            ldmx4(BL[nb], pbase + sw128(o + 64));
        }
#pragma unroll
        for (int mf = 0; mf < 4; mf++)
#pragma unroll
            for (int nb = 0; nb < 2; nb++)
#pragma unroll
                for (int ns = 0; ns < 2; ns++) {
                    float* c = acc[mf][nb*2 + ns];
                    mma_bf16(c, AH[mf], BH[nb][ns*2], BH[nb][ns*2+1]);
                    mma_bf16(c, AH[mf], BL[nb][ns*2], BL[nb][ns*2+1]);
                    mma_bf16(c, AL[mf], BH[nb][ns*2], BH[nb][ns*2+1]);
                }
    };

    loadA(0, 0); loadB(0, 0); cp_commit();
    cp_wait0(); __syncthreads();

    for (int c = 0; c < 16; c++) {
        const int cur = c & 1, nxt = cur ^ 1;
        if (c < 15) { loadA(c+1, nxt); loadB(c+1, nxt); cp_commit(); }
        mma_step(cur, 0);
        mma_step(cur, 1);
        if (c < 15) { cp_wait0(); }
        __syncthreads();
    }

#pragma unroll
    for (int mf = 0; mf < 4; mf++)
#pragma unroll
        for (int nf = 0; nf < 4; nf++) {
            const float* cc = acc[mf][nf];
            int j   = j0 + wm*64 + mf*16 + (l >> 2);
            int col = n0 + wn*32 + nf*8 + (l & 3)*2;
            int k = col >> 9, d = col & 511;
            float* dst = g_proj + ((size_t)(b*KQ + k)*NQ + j)*DQ + d;
            *(float2*)dst          = make_float2(cc[0], cc[1]);
            *(float2*)(dst + 8*DQ) = make_float2(cc[2], cc[3]);
        }
}

// ---------------------------------------------------------------------------
// Kernel A2: transpose + mass-scale + bf16 hi/lo split of proj
// ---------------------------------------------------------------------------
__global__ __launch_bounds__(256) void split_t_kernel(const float* __restrict__ mass)
{
    __shared__ float tile[32][33];
    const int bk = blockIdx.z;
    const int j0 = blockIdx.x * 32, d0 = blockIdx.y * 32;
    const int tx = threadIdx.x & 31, ty = threadIdx.x >> 5;
    const float* src = g_proj + ((size_t)bk*NQ + j0)*DQ + d0;
#pragma unroll
    for (int r = 0; r < 4; r++)
        tile[r*8+ty][tx] = src[(size_t)(r*8+ty)*DQ + tx];
    __syncthreads();
    const int b = bk >> 2;
    const float mj = mass[(size_t)b*NQ + j0 + tx];
    const size_t ob = ((size_t)bk*DQ + d0)*NQ + j0;
#pragma unroll
    for (int r = 0; r < 4; r++) {
        int d = r*8 + ty;
        float v = tile[tx][d] * mj;
        __nv_bfloat16 h = __float2bfloat16(v);
        __nv_bfloat16 l = __float2bfloat16(v - __bfloat162float(h));
        g_pT_hi[ob + (size_t)d*NQ + tx] = h;
        g_pT_lo[ob + (size_t)d*NQ + tx] = l;
    }
}

// ---------------------------------------------------------------------------
// Kernel W: weight generation (unchanged, 52us)
// ---------------------------------------------------------------------------
__global__ __launch_bounds__(256) void wgen_kernel(
    const float* __restrict__ position, const float* __restrict__ lbw)
{
    __shared__ float posI[128*16];
    const int b = blockIdx.z, i0 = blockIdx.y*128, j0 = blockIdx.x*128;
    const int t = threadIdx.x;

    for (int u = t; u < 512; u += 256) {
        int r = u >> 2, q = u & 3;
        *(float4*)&posI[r*16 + q*4] =
            *(const float4*)(position + ((size_t)b*NQ + i0 + r)*PQ + q*4);
    }

    float negc[4];
#pragma unroll
    for (int k = 0; k < 4; k++) negc[k] = -1.0f/(2.0f*__expf(lbw[k]) + 1e-8f);
    const bool eq[4] = {false, negc[1] == negc[0], negc[2] == negc[0], negc[3] == negc[0]};

    const int jp = (t & 63)*2;
    const int ig = t >> 6;

    float pj[32];
#pragma unroll
    for (int u2 = 0; u2 < 2; u2++) {
        const float* p = position + ((size_t)b*NQ + j0 + jp + u2)*PQ;
#pragma unroll
        for (int q = 0; q < 16; q += 4) {
            float4 v = *(const float4*)(p + q);
            pj[u2*16+q] = v.x; pj[u2*16+q+1] = v.y;
            pj[u2*16+q+2] = v.z; pj[u2*16+q+3] = v.w;
        }
    }
    __syncthreads();

    for (int ii = 0; ii < 32; ii++) {
        const int i = ig*32 + ii;
        const float* pi = &posI[i*16];
        float d2a = 0.f, d2b = 0.f;
#pragma unroll
        for (int q = 0; q < 16; q++) {
            float piq = pi[q];
            float da = piq - pj[q], db = piq - pj[16+q];
            d2a = fmaf(da, da, d2a); d2b = fmaf(db, db, d2b);
        }
        float ea[4], eb[4];
        ea[0] = __expf(d2a*negc[0]);
        eb[0] = __expf(d2b*negc[0]);
#pragma unroll
        for (int k = 1; k < 4; k++) {
            ea[k] = eq[k] ? ea[0] : __expf(d2a*negc[k]);
            eb[k] = eq[k] ? eb[0] : __expf(d2b*negc[k]);
        }
#pragma unroll
        for (int k = 0; k < 4; k++) {
            __nv_bfloat162 h2, l2;
            h2.x = __float2bfloat16(ea[k]);
            h2.y = __float2bfloat16(eb[k]);
            l2.x = __float2bfloat16(ea[k] - __bfloat162float(h2.x));
            l2.y = __float2bfloat16(eb[k] - __bfloat162float(h2.y));
            size_t off = ((size_t)(b*KQ + k)*NQ + i0 + i)*NQ + j0 + jp;
            *(__nv_bfloat162*)(g_wh + off) = h2;
            *(__nv_bfloat162*)(g_wl + off) = l2;
        }
    }
}

// ---------------------------------------------------------------------------
// Kernel B: field GEMM (unchanged from R6, passing)
// ---------------------------------------------------------------------------
__global__ __launch_bounds__(256, 1) void field_gemm_kernel()
{
    extern __shared__ char smc[];
    const unsigned sb = smem_u32(smc);
    const int t = threadIdx.x, l = t & 31, w = t >> 5;
    const int wm = w & 1, wn = w >> 1;
    const int i0 = blockIdx.x * 128, d0 = blockIdx.y * 128;
    const int bk = blockIdx.z;

    const unsigned aOffB = (unsigned)((wm*64 + (l & 15))*128 + (l >> 4)*16);
    const unsigned bRowB = (unsigned)((l & 7) + ((l >> 4) & 1)*8);
    const unsigned bKH   = (unsigned)(((l >> 3) & 1)*16);

    float acc[4][4][4];
#pragma unroll
    for (int a = 0; a < 4; a++)
#pragma unroll
        for (int n = 0; n < 4; n++)
#pragma unroll
            for (int q = 0; q < 4; q++) acc[a][n][q] = 0.0f;

    auto loadA = [&](int c, int buf) {
        int row = t >> 1, sel = t & 1;
        const __nv_bfloat16* src = (sel ? g_wl : g_wh) +
            ((size_t)bk*NQ + i0 + row)*NQ + c*32;
        unsigned dst = sb + FG_A + buf*16384;
        unsigned base = (unsigned)(row*128 + sel*64);
#pragma unroll
        for (int cc = 0; cc < 4; cc++)
            cp16(dst + sw128(base + cc*16), (const char*)src + cc*16);
    };
    auto loadB = [&](int c, int buf) {
        int row = t >> 1, sel = t & 1;
        const __nv_bfloat16* src = (sel ? g_pT_lo : g_pT_hi) +
            ((size_t)bk*DQ + d0 + row)*NQ + c*32;
        unsigned dst = sb + FG_B + buf*16384;
        unsigned base = (unsigned)(row*128 + sel*64);
#pragma unroll
        for (int cc = 0; cc < 4; cc++)
            cp16(dst + sw128(base + cc*16), (const char*)src + cc*16);
    };

    auto mma_step = [&](int buf, int ks) {
        const unsigned abase = sb + FG_A + buf*16384;
        const unsigned pbase = sb + FG_B + buf*16384;
        uint32_t AH[4][4], AL[4][4], BH[2][4], BL[2][4];
#pragma unroll
        for (int mf = 0; mf < 4; mf++) {
            unsigned o = aOffB + mf*2048 + ks*32;
            ldmx4(AH[mf], abase + sw128(o));
            ldmx4(AL[mf], abase + sw128(o + 64));
        }
#pragma unroll
        for (int nb = 0; nb < 2; nb++) {
            unsigned o = (bRowB + wn*32 + nb*16)*128 + bKH + ks*32;
            ldmx4(BH[nb], pbase + sw128(o));
            ldmx4(BL[nb], pbase + sw128(o + 64));
        }
#pragma unroll
        for (int mf = 0; mf < 4; mf++)
#pragma unroll
            for (int nb = 0; nb < 2; nb++)
#pragma unroll
                for (int ns = 0; ns < 2; ns++) {
                    float* c = acc[mf][nb*2 + ns];
                    mma_bf16(c, AH[mf], BH[nb][ns*2], BH[nb][ns*2+1]);
                    mma_bf16(c, AH[mf], BL[nb][ns*2], BL[nb][ns*2+1]);
                    mma_bf16(c, AL[mf], BH[nb][ns*2], BH[nb][ns*2+1]);
                }
    };

    loadA(0, 0); loadB(0, 0); cp_commit();
    cp_wait0(); __syncthreads();

    for (int c = 0; c < 64; c++) {
        const int cur = c & 1, nxt = cur ^ 1;
        if (c < 63) { loadA(c+1, nxt); loadB(c+1, nxt); cp_commit(); }
        mma_step(cur, 0);
        mma_step(cur, 1);
        if (c < 63) { cp_wait0(); }
        __syncthreads();
    }

#pragma unroll
    for (int mf = 0; mf < 4; mf++)
#pragma unroll
        for (int nf = 0; nf < 4; nf++) {
            const float* cc = acc[mf][nf];
            int i = i0 + wm*64 + mf*16 + (l >> 2);
            int d = d0 + wn*32 + nf*8 + (l & 3)*2;
            size_t o1 = ((size_t)bk*NQ + i)*DQ + d;
            size_t o2 = o1 + (size_t)8*DQ;
            __nv_bfloat162 h2, l2;
            h2.x = __float2bfloat16(cc[0]); h2.y = __float2bfloat16(cc[1]);
            l2.x = __float2bfloat16(cc[0] - __bfloat162float(h2.x));
            l2.y = __float2bfloat16(cc[1] - __bfloat162float(h2.y));
            *(__nv_bfloat162*)(g_fh + o1) = h2;
            *(__nv_bfloat162*)(g_fl + o1) = l2;
            h2.x = __float2bfloat16(cc[2]); h2.y = __float2bfloat16(cc[3]);
            l2.x = __float2bfloat16(cc[2] - __bfloat162float(h2.x));
            l2.y = __float2bfloat16(cc[3] - __bfloat162float(h2.y));
            *(__nv_bfloat162*)(g_fh + o2) = h2;
            *(__nv_bfloat162*)(g_fl + o2) = l2;
        }
}

// ---------------------------------------------------------------------------
// Kernel C v3: 64-row i-tile combine + LN. Block: 64 i x 512 dout, 256 thr.
// K=2048 in 128 chunks of 16. B frags loaded just-in-time (register economy).
// ---------------------------------------------------------------------------
__global__ __launch_bounds__(256, 1) void combine_mma_kernel(
    const float* __restrict__ gammaP, const float* __restrict__ betaP,
    float* __restrict__ out)
{
    extern __shared__ char smc[];
    const unsigned sb = smem_u32(smc);
    const int t = threadIdx.x, l = t & 31, w = t >> 5;
    const int i0 = blockIdx.x * 64;
    const int b  = blockIdx.y;

    float* rowSum = (float*)(smc + CM_LN);          // 64 x 32
    float* rowSq  = rowSum + 2048;
    float* gammaS = (float*)(smc + CM_GB);
    float* betaS  = gammaS + 512;
    __shared__ float meanS[64], rsS[64];

    for (int u = t; u < 512; u += 256) { gammaS[u] = gammaP[u]; betaS[u] = betaP[u]; }

    float acc[4][8][4];
#pragma unroll
    for (int mf = 0; mf < 4; mf++)
#pragma unroll
        for (int nf = 0; nf < 8; nf++)
#pragma unroll
            for (int q = 0; q < 4; q++) acc[mf][nf][q] = 0.0f;

    auto loadA = [&](int c, int buf) {    // 64 rows x 16 kd, hi|lo in 64B rows
        int row = t >> 2, s = t & 3, sel = s >> 1, h = s & 1;
        int k = c >> 5, d0 = (c & 31)*16;
        const __nv_bfloat16* src = (sel ? g_fl : g_fh) +
            ((size_t)(b*KQ + k)*NQ + i0 + row)*DQ + d0 + h*8;
        cp16(sb + CM_A + buf*4096 + sw64row(row, sel*32 + h*16), src);
    };
    auto loadB = [&](int c, int buf) {
        unsigned dst = sb + CM_B + buf*32768;
#pragma unroll
        for (int rr = 0; rr < 2; rr++) {
            int row = t*2 + rr;
            const __nv_bfloat16* srcH = g_cbh + (size_t)row*KDQ + c*16;
            const __nv_bfloat16* srcL = g_cbl + (size_t)row*KDQ + c*16;
            cp16(dst + sw64row(row, 0),  srcH);
            cp16(dst + sw64row(row, 16), srcH + 8);
            cp16(dst + sw64row(row, 32), srcL);
            cp16(dst + sw64row(row, 48), srcL + 8);
        }
    };

    const unsigned aRow = (unsigned)(l & 15);
    const unsigned aH   = (unsigned)((l >> 4)*16);
    const unsigned bRow = (unsigned)((l & 7) + ((l >> 4) & 1)*8);
    const unsigned bH   = (unsigned)(((l >> 3) & 1)*16);

    loadA(0, 0); loadB(0, 0); cp_commit();
    cp_wait0(); __syncthreads();

    for (int c = 0; c < 128; c++) {
        const int cur = c & 1, nxt = cur ^ 1;
        if (c + 1 < 128) { loadA(c+1, nxt); loadB(c+1, nxt); }
        cp_commit();

        const unsigned abase = sb + CM_A + cur*4096;
        const unsigned bbase = sb + CM_B + cur*32768;
        uint32_t AH[4][4], AL[4][4];
#pragma unroll
        for (int mf = 0; mf < 4; mf++) {
            unsigned r = mf*16 + aRow;
            ldmx4(AH[mf], abase + sw64row(r, aH));
            ldmx4(AL[mf], abase + sw64row(r, 32 + aH));
        }
#pragma unroll
        for (int nb = 0; nb < 4; nb++) {
            uint32_t BH[4], BL[4];
            unsigned r = w*64 + nb*16 + bRow;
            ldmx4(BH, bbase + sw64row(r, bH));
            ldmx4(BL, bbase + sw64row(r, 32 + bH));
#pragma unroll
            for (int mf = 0; mf < 4; mf++)
#pragma unroll
                for (int ns = 0; ns < 2; ns++) {
                    float* cc = acc[mf][nb*2 + ns];
                    mma_bf16(cc, AH[mf], BH[ns*2], BH[ns*2+1]);
                    mma_bf16(cc, AH[mf], BL[ns*2], BL[ns*2+1]);
                    mma_bf16(cc, AL[mf], BH[ns*2], BH[ns*2+1]);
                }
        }

        if (c + 1 < 128) { cp_wait0(); }
        __syncthreads();
    }

    // ---- LayerNorm over 64 rows ----
    const int cw = w*4 + (l & 3);
#pragma unroll
    for (int mf = 0; mf < 4; mf++) {
        float sLo = 0.f, sHi = 0.f, qLo = 0.f, qHi = 0.f;
#pragma unroll
        for (int nf = 0; nf < 8; nf++) {
            const float* cc = acc[mf][nf];
            sLo += cc[0] + cc[1];  qLo += cc[0]*cc[0] + cc[1]*cc[1];
            sHi += cc[2] + cc[3];  qHi += cc[2]*cc[2] + cc[3]*cc[3];
        }
        int rLo = mf*16 + (l >> 2), rHi = rLo + 8;
        rowSum[rLo*32 + cw] = sLo;  rowSq[rLo*32 + cw] = qLo;
        rowSum[rHi*32 + cw] = sHi;  rowSq[rHi*32 + cw] = qHi;
    }
    __syncthreads();
#pragma unroll
    for (int rr = 0; rr < 8; rr++) {
        int row = w*8 + rr;
        float s  = rowSum[row*32 + l];
        float s2 = rowSq [row*32 + l];
#pragma unroll
        for (int off = 16; off > 0; off >>= 1) {
            s  += __shfl_xor_sync(0xffffffffu, s,  off);
            s2 += __shfl_xor_sync(0xffffffffu, s2, off);
        }
        if (l == 0) {
            float mean = s * (1.0f/512.0f);
            float var  = s2 * (1.0f/512.0f) - mean*mean;
            meanS[row] = mean;
            rsS[row]   = rsqrtf(var + 1e-5f);
        }
    }
    __syncthreads();

#pragma unroll
    for (int mf = 0; mf < 4; mf++)
#pragma unroll
        for (int nf = 0; nf < 8; nf++) {
            const float* cc = acc[mf][nf];
            int dout = w*64 + nf*8 + (l & 3)*2;
            float g0 = gammaS[dout], g1 = gammaS[dout+1];
            float b0 = betaS[dout],  b1 = betaS[dout+1];
            int rLo = mf*16 + (l >> 2), rHi = rLo + 8;
            float mLo = meanS[rLo], rsLo = rsS[rLo];
            float mHi = meanS[rHi], rsHi = rsS[rHi];
            float* dLo = out + ((size_t)b*NQ + i0 + rLo)*DQ + dout;
            float* dHi = out + ((size_t)b*NQ + i0 + rHi)*DQ + dout;
            *(float2*)dLo = make_float2((cc[0]-mLo)*rsLo*g0 + b0,
                                        (cc[1]-mLo)*rsLo*g1 + b1);
            *(float2*)dHi = make_float2((cc[2]-mHi)*rsHi*g0 + b0,
                                        (cc[3]-mHi)*rsHi*g1 + b1);
        }
}

// ---------------------------------------------------------------------------
extern "C" void kernel_launch(void* const* d_in, const int* in_sizes, int n_in,
                              void* d_out, int out_size)
{
    const float* charge   = (const float*)d_in[0];
    const float* position = (const float*)d_in[1];
    const float* mass     = (const float*)d_in[2];
    const float* lbw      = (const float*)d_in[3];
    const float* Wch      = (const float*)d_in[4];
    const float* Wcb      = (const float*)d_in[5];
    const float* gammaP   = (const float*)d_in[6];
    const float* betaP    = (const float*)d_in[7];
    float* out = (float*)d_out;

    cudaFuncSetAttribute(proj_mma_kernel,
                         cudaFuncAttributeMaxDynamicSharedMemorySize, SMEM_FG);
    cudaFuncSetAttribute(field_gemm_kernel,
                         cudaFuncAttributeMaxDynamicSharedMemorySize, SMEM_FG);
    cudaFuncSetAttribute(combine_mma_kernel,
                         cudaFuncAttributeMaxDynamicSharedMemorySize, SMEM_COMB);

    split_ch_kernel  <<<(BQ*NQ*DQ)/1024, 256>>>(charge);
    split_cw_kernel  <<<(KDQ*DQ)/1024, 256>>>(Wch);
    split_cb_kernel  <<<(DQ*KDQ)/1024, 256>>>(Wcb);
    proj_mma_kernel  <<<dim3(NQ/128, KDQ/128, BQ), 256, SMEM_FG>>>();
    split_t_kernel   <<<dim3(NQ/32, DQ/32, BQ*KQ), 256>>>(mass);
    wgen_kernel      <<<dim3(NQ/128, NQ/128, BQ), 256>>>(position, lbw);
    field_gemm_kernel<<<dim3(NQ/128, DQ/128, BQ*KQ), 256, SMEM_FG>>>();
    combine_mma_kernel<<<dim3(NQ/64, BQ), 256, SMEM_COMB>>>(gammaP, betaP, out);
}

// round 10
// speedup vs baseline: 2.3454x; 1.0095x over previous
#include <cuda_runtime.h>
#include <cuda_bf16.h>
#include <cstdint>

// Problem constants
#define BQ 4
#define NQ 2048
#define DQ 512
#define PQ 16
#define KQ 4
#define KDQ (KQ*DQ)

// Scratch
__device__ __nv_bfloat16 g_pT_hi[(size_t)BQ*KQ*DQ*NQ];   // [bk][d][j]  (mass folded in)
__device__ __nv_bfloat16 g_pT_lo[(size_t)BQ*KQ*DQ*NQ];
__device__ __nv_bfloat16 g_fh[(size_t)BQ*KQ*NQ*DQ];      // field bf16 hi  [bk][i][d]
__device__ __nv_bfloat16 g_fl[(size_t)BQ*KQ*NQ*DQ];      // field bf16 lo
__device__ __nv_bfloat16 g_cbh[(size_t)DQ*KDQ];          // W_combine hi [dout][kd]
__device__ __nv_bfloat16 g_cbl[(size_t)DQ*KDQ];          // W_combine lo
__device__ __nv_bfloat16 g_wh[(size_t)BQ*KQ*NQ*NQ];      // weights hi [bk][i][j]
__device__ __nv_bfloat16 g_wl[(size_t)BQ*KQ*NQ*NQ];      // weights lo
__device__ __nv_bfloat16 g_chh[(size_t)BQ*NQ*DQ];        // charge hi [b][j][c]
__device__ __nv_bfloat16 g_chl[(size_t)BQ*NQ*DQ];
__device__ __nv_bfloat16 g_cwh[(size_t)KDQ*DQ];          // W_charge hi [kd][c]
__device__ __nv_bfloat16 g_cwl[(size_t)KDQ*DQ];

// ---------------------------------------------------------------------------
// helpers (portable PTX only: cp.async / ldmatrix / mma.sync — sm_80+ baseline)
// ---------------------------------------------------------------------------
__device__ __forceinline__ unsigned smem_u32(const void* p) {
    return (unsigned)__cvta_generic_to_shared(p);
}
__device__ __forceinline__ void cp16(unsigned dst, const void* src) {
    asm volatile("cp.async.cg.shared.global [%0], [%1], 16;" :: "r"(dst), "l"(src));
}
__device__ __forceinline__ void cp_commit() { asm volatile("cp.async.commit_group;"); }
__device__ __forceinline__ void cp_wait0()  { asm volatile("cp.async.wait_group 0;"); }
__device__ __forceinline__ void cp_wait1()  { asm volatile("cp.async.wait_group 1;"); }

__device__ __forceinline__ unsigned sw128(unsigned o) {   // SW128: bits[6:4] ^= bits[9:7]
    return o ^ ((o >> 3) & 0x70u);
}
__device__ __forceinline__ unsigned sw64row(unsigned row, unsigned seg) {
    return row*64u + (seg ^ ((row & 6u) << 3));
}

__device__ __forceinline__ void ldmx4(uint32_t* r, unsigned addr) {
    asm volatile("ldmatrix.sync.aligned.m8n8.x4.shared.b16 {%0,%1,%2,%3}, [%4];"
                 : "=r"(r[0]), "=r"(r[1]), "=r"(r[2]), "=r"(r[3]) : "r"(addr));
}

__device__ __forceinline__ void mma_bf16(float* c, const uint32_t* a,
                                         uint32_t b0, uint32_t b1) {
    asm volatile("mma.sync.aligned.m16n8k16.row.col.f32.bf16.bf16.f32 "
                 "{%0,%1,%2,%3}, {%4,%5,%6,%7}, {%8,%9}, {%0,%1,%2,%3};"
                 : "+f"(c[0]), "+f"(c[1]), "+f"(c[2]), "+f"(c[3])
                 : "r"(a[0]), "r"(a[1]), "r"(a[2]), "r"(a[3]), "r"(b0), "r"(b1));
}

__device__ __forceinline__ uint32_t pack_bf2(__nv_bfloat16 a, __nv_bfloat16 b) {
    return (uint32_t)__bfloat16_as_ushort(a) | ((uint32_t)__bfloat16_as_ushort(b) << 16);
}

// proj kernel smem: loop A 2x16KB | B 2x16KB; epilogue reuses as 128x132 fp32
#define PJ_A   0
#define PJ_B   32768
#define SMEM_PJ 67584          // 128*132*4 (epilogue transpose stage, float4-aligned pad)

// field GEMM smem: 3-stage ring, A 3x16KB | B 3x16KB
#define FG_A   0
#define FG_B   49152
#define SMEM_FG 98304

// combine kernel smem layout (64-row i-tile)
#define CM_A   0          // 2 x 4KB
#define CM_B   8192       // 2 x 32KB
#define CM_LN  73728      // rowSum 8KB | rowSq 8KB
#define CM_GB  90112      // gamma 2KB | beta 2KB
#define SMEM_COMB 94208

// ---------------------------------------------------------------------------
// Elementwise bf16 hi/lo split kernels
// ---------------------------------------------------------------------------
__global__ __launch_bounds__(256) void split_ch_kernel(const float* __restrict__ src)
{
    const size_t idx = (size_t)blockIdx.x*1024 + threadIdx.x*4;
    float4 v = *(const float4*)(src + idx);
    float vv[4] = {v.x, v.y, v.z, v.w};
#pragma unroll
    for (int q = 0; q < 4; q++) {
        __nv_bfloat16 h = __float2bfloat16(vv[q]);
        g_chh[idx + q] = h;
        g_chl[idx + q] = __float2bfloat16(vv[q] - __bfloat162float(h));
    }
}
__global__ __launch_bounds__(256) void split_cw_kernel(const float* __restrict__ src)
{
    const size_t idx = (size_t)blockIdx.x*1024 + threadIdx.x*4;
    float4 v = *(const float4*)(src + idx);
    float vv[4] = {v.x, v.y, v.z, v.w};
#pragma unroll
    for (int q = 0; q < 4; q++) {
        __nv_bfloat16 h = __float2bfloat16(vv[q]);
        g_cwh[idx + q] = h;
        g_cwl[idx + q] = __float2bfloat16(vv[q] - __bfloat162float(h));
    }
}
__global__ __launch_bounds__(256) void split_cb_kernel(const float* __restrict__ Wcb)
{
    const size_t idx = (size_t)blockIdx.x*1024 + threadIdx.x*4;
    float4 v = *(const float4*)(Wcb + idx);
    float vv[4] = {v.x, v.y, v.z, v.w};
#pragma unroll
    for (int q = 0; q < 4; q++) {
        __nv_bfloat16 h = __float2bfloat16(vv[q]);
        g_cbh[idx + q] = h;
        g_cbl[idx + q] = __float2bfloat16(vv[q] - __bfloat162float(h));
    }
}

// ---------------------------------------------------------------------------
// Kernel A (tensor): proj = charge @ Wch^T, fused epilogue:
// transpose + mass-scale + bf16 hi/lo split -> g_pT[bk][d][j] directly.
// 128(j) x 128(kd) tiles, K=512 in 16 chunks, 3-way bf16 split.
// ---------------------------------------------------------------------------
__global__ __launch_bounds__(256, 1) void proj_mma_kernel(const float* __restrict__ mass)
{
    extern __shared__ char smc[];
    const unsigned sb = smem_u32(smc);
    const int t = threadIdx.x, l = t & 31, w = t >> 5;
    const int wm = w & 1, wn = w >> 1;
    const int j0 = blockIdx.x * 128, n0 = blockIdx.y * 128;
    const int b = blockIdx.z;

    __shared__ float massS[128];
    if (t < 128) massS[t] = mass[(size_t)b*NQ + j0 + t];

    const unsigned aOffB = (unsigned)((wm*64 + (l & 15))*128 + (l >> 4)*16);
    const unsigned bRowB = (unsigned)((l & 7) + ((l >> 4) & 1)*8);
    const unsigned bKH   = (unsigned)(((l >> 3) & 1)*16);

    float acc[4][4][4];
#pragma unroll
    for (int a = 0; a < 4; a++)
#pragma unroll
        for (int n = 0; n < 4; n++)
#pragma unroll
            for (int q = 0; q < 4; q++) acc[a][n][q] = 0.0f;

    auto loadA = [&](int c, int buf) {
        int row = t >> 1, sel = t & 1;
        const __nv_bfloat16* src = (sel ? g_chl : g_chh) +
            ((size_t)b*NQ + j0 + row)*DQ + c*32;
        unsigned dst = sb + PJ_A + buf*16384;
        unsigned base = (unsigned)(row*128 + sel*64);
#pragma unroll
        for (int cc = 0; cc < 4; cc++)
            cp16(dst + sw128(base + cc*16), (const char*)src + cc*16);
    };
    auto loadB = [&](int c, int buf) {
        int row = t >> 1, sel = t & 1;
        const __nv_bfloat16* src = (sel ? g_cwl : g_cwh) +
            (size_t)(n0 + row)*DQ + c*32;
        unsigned dst = sb + PJ_B + buf*16384;
        unsigned base = (unsigned)(row*128 + sel*64);
#pragma unroll
        for (int cc = 0; cc < 4; cc++)
            cp16(dst + sw128(base + cc*16), (const char*)src + cc*16);
    };

    auto mma_step = [&](int buf, int ks) {
        const unsigned abase = sb + PJ_A + buf*16384;
        const unsigned pbase = sb + PJ_B + buf*16384;
        uint32_t AH[4][4], AL[4][4], BH[2][4], BL[2][4];
#pragma unroll
        for (int mf = 0; mf < 4; mf++) {
            unsigned o = aOffB + mf*2048 + ks*32;
            ldmx4(AH[mf], abase + sw128(o));
            ldmx4(AL[mf], abase + sw128(o + 64));
        }
#pragma unroll
        for (int nb = 0; nb < 2; nb++) {
            unsigned o = (bRowB + wn*32 + nb*16)*128 + bKH + ks*32;
            ldmx4(BH[nb], pbase + sw128(o));
            ldmx4(BL[nb], pbase + sw128(o + 64));
        }
#pragma unroll
        for (int mf = 0; mf < 4; mf++)
#pragma unroll
            for (int nb = 0; nb < 2; nb++)
#pragma unroll
                for (int ns = 0; ns < 2; ns++) {
                    float* c = acc[mf][nb*2 + ns];
                    mma_bf16(c, AH[mf], BH[nb][ns*2], BH[nb][ns*2+1]);
                    mma_bf16(c, AH[mf], BL[nb][ns*2], BL[nb][ns*2+1]);
                    mma_bf16(c, AL[mf], BH[nb][ns*2], BH[nb][ns*2+1]);
                }
    };

    loadA(0, 0); loadB(0, 0); cp_commit();
    cp_wait0(); __syncthreads();

    for (int c = 0; c < 16; c++) {
        const int cur = c & 1, nxt = cur ^ 1;
        if (c < 15) { loadA(c+1, nxt); loadB(c+1, nxt); cp_commit(); }
        mma_step(cur, 0);
        mma_step(cur, 1);
        if (c < 15) { cp_wait0(); }
        __syncthreads();
    }

    // ---- fused epilogue: stage transposed fp32 tile, then mass+split+store --
    // pad 132 (multiple of 4) keeps float4 reads 16B-aligned for every cl.
    float* tile = (float*)smc;             // 128 cols x 132 (padded) j
#pragma unroll
    for (int mf = 0; mf < 4; mf++)
#pragma unroll
        for (int nf = 0; nf < 4; nf++) {
            const float* cc = acc[mf][nf];
            int jl = wm*64 + mf*16 + (l >> 2);
            int cl = wn*32 + nf*8 + (l & 3)*2;
            tile[(cl  )*132 + jl    ] = cc[0];
            tile[(cl+1)*132 + jl    ] = cc[1];
            tile[(cl  )*132 + jl + 8] = cc[2];
            tile[(cl+1)*132 + jl + 8] = cc[3];
        }
    __syncthreads();

    const int jl = l*4;
    const float4 mv = *(const float4*)&massS[jl];
#pragma unroll
    for (int r = 0; r < 16; r++) {
        int cl = w*16 + r;
        float4 v = *(const float4*)&tile[cl*132 + jl];
        float x0 = v.x*mv.x, x1 = v.y*mv.y, x2 = v.z*mv.z, x3 = v.w*mv.w;
        __nv_bfloat16 h0 = __float2bfloat16(x0), h1 = __float2bfloat16(x1);
        __nv_bfloat16 h2 = __float2bfloat16(x2), h3 = __float2bfloat16(x3);
        __nv_bfloat16 l0 = __float2bfloat16(x0 - __bfloat162float(h0));
        __nv_bfloat16 l1 = __float2bfloat16(x1 - __bfloat162float(h1));
        __nv_bfloat16 l2 = __float2bfloat16(x2 - __bfloat162float(h2));
        __nv_bfloat16 l3 = __float2bfloat16(x3 - __bfloat162float(h3));
        int colG = n0 + cl;
        int k = colG >> 9, d = colG & 511;
        size_t ob = ((size_t)(b*KQ + k)*DQ + d)*NQ + j0 + jl;
        uint2 hv = make_uint2(pack_bf2(h0, h1), pack_bf2(h2, h3));
        uint2 lv = make_uint2(pack_bf2(l0, l1), pack_bf2(l2, l3));
        *(uint2*)(g_pT_hi + ob) = hv;
        *(uint2*)(g_pT_lo + ob) = lv;
    }
}

// ---------------------------------------------------------------------------
// Kernel W: weight generation. Writes k=0 always; k>0 only if its bandwidth
// differs from k=0 (field kernel folds equal-k reads to slice 0).
// ---------------------------------------------------------------------------
__global__ __launch_bounds__(256) void wgen_kernel(
    const float* __restrict__ position, const float* __restrict__ lbw)
{
    __shared__ float posI[128*16];
    const int b = blockIdx.z, i0 = blockIdx.y*128, j0 = blockIdx.x*128;
    const int t = threadIdx.x;

    for (int u = t; u < 512; u += 256) {
        int r = u >> 2, q = u & 3;
        *(float4*)&posI[r*16 + q*4] =
            *(const float4*)(position + ((size_t)b*NQ + i0 + r)*PQ + q*4);
    }

    float negc[4];
#pragma unroll
    for (int k = 0; k < 4; k++) negc[k] = -1.0f/(2.0f*__expf(lbw[k]) + 1e-8f);
    const bool eq[4] = {false, negc[1] == negc[0], negc[2] == negc[0], negc[3] == negc[0]};

    const int jp = (t & 63)*2;
    const int ig = t >> 6;

    float pj[32];
#pragma unroll
    for (int u2 = 0; u2 < 2; u2++) {
        const float* p = position + ((size_t)b*NQ + j0 + jp + u2)*PQ;
#pragma unroll
        for (int q = 0; q < 16; q += 4) {
            float4 v = *(const float4*)(p + q);
            pj[u2*16+q] = v.x; pj[u2*16+q+1] = v.y;
            pj[u2*16+q+2] = v.z; pj[u2*16+q+3] = v.w;
        }
    }
    __syncthreads();

    for (int ii = 0; ii < 32; ii++) {
        const int i = ig*32 + ii;
        const float* pi = &posI[i*16];
        float d2a = 0.f, d2b = 0.f;
#pragma unroll
        for (int q = 0; q < 16; q++) {
            float piq = pi[q];
            float da = piq - pj[q], db = piq - pj[16+q];
            d2a = fmaf(da, da, d2a); d2b = fmaf(db, db, d2b);
        }
#pragma unroll
        for (int k = 0; k < 4; k++) {
            if (k > 0 && eq[k]) continue;       // slice never read (folded to 0)
            float ea = __expf(d2a*negc[k]);
            float eb = __expf(d2b*negc[k]);
            __nv_bfloat162 h2, l2;
            h2.x = __float2bfloat16(ea);
            h2.y = __float2bfloat16(eb);
            l2.x = __float2bfloat16(ea - __bfloat162float(h2.x));
            l2.y = __float2bfloat16(eb - __bfloat162float(h2.y));
            size_t off = ((size_t)(b*KQ + k)*NQ + i0 + i)*NQ + j0 + jp;
            *(__nv_bfloat162*)(g_wh + off) = h2;
            *(__nv_bfloat162*)(g_wl + off) = l2;
        }
    }
}

// ---------------------------------------------------------------------------
// Kernel B: field GEMM, 3-stage cp.async ring. A-base folds k with equal
// bandwidth to slice 0 (L2 sharing across k).
// ---------------------------------------------------------------------------
__global__ __launch_bounds__(256, 1) void field_gemm_kernel(const float* __restrict__ lbw)
{
    extern __shared__ char smc[];
    const unsigned sb = smem_u32(smc);
    const int t = threadIdx.x, l = t & 31, w = t >> 5;
    const int wm = w & 1, wn = w >> 1;
    const int i0 = blockIdx.x * 128, d0 = blockIdx.y * 128;
    const int bk = blockIdx.z, b = bk >> 2, k = bk & 3;

    const float nc0 = -1.0f/(2.0f*__expf(lbw[0]) + 1e-8f);
    const float nck = -1.0f/(2.0f*__expf(lbw[k]) + 1e-8f);
    const int ksrc = (nck == nc0) ? 0 : k;
    const size_t wbase_g = (size_t)(b*KQ + ksrc)*NQ*NQ;

    const unsigned aOffB = (unsigned)((wm*64 + (l & 15))*128 + (l >> 4)*16);
    const unsigned bRowB = (unsigned)((l & 7) + ((l >> 4) & 1)*8);
    const unsigned bKH   = (unsigned)(((l >> 3) & 1)*16);

    float acc[4][4][4];
#pragma unroll
    for (int a = 0; a < 4; a++)
#pragma unroll
        for (int n = 0; n < 4; n++)
#pragma unroll
            for (int q = 0; q < 4; q++) acc[a][n][q] = 0.0f;

    auto loadA = [&](int c, int buf) {
        int row = t >> 1, sel = t & 1;
        const __nv_bfloat16* src = (sel ? g_wl : g_wh) +
            wbase_g + (size_t)(i0 + row)*NQ + c*32;
        unsigned dst = sb + FG_A + buf*16384;
        unsigned base = (unsigned)(row*128 + sel*64);
#pragma unroll
        for (int cc = 0; cc < 4; cc++)
            cp16(dst + sw128(base + cc*16), (const char*)src + cc*16);
    };
    auto loadB = [&](int c, int buf) {
        int row = t >> 1, sel = t & 1;
        const __nv_bfloat16* src = (sel ? g_pT_lo : g_pT_hi) +
            ((size_t)bk*DQ + d0 + row)*NQ + c*32;
        unsigned dst = sb + FG_B + buf*16384;
        unsigned base = (unsigned)(row*128 + sel*64);
#pragma unroll
        for (int cc = 0; cc < 4; cc++)
            cp16(dst + sw128(base + cc*16), (const char*)src + cc*16);
    };

    auto mma_step = [&](int buf, int ks) {
        const unsigned abase = sb + FG_A + buf*16384;
        const unsigned pbase = sb + FG_B + buf*16384;
        uint32_t AH[4][4], AL[4][4], BH[2][4], BL[2][4];
#pragma unroll
        for (int mf = 0; mf < 4; mf++) {
            unsigned o = aOffB + mf*2048 + ks*32;
            ldmx4(AH[mf], abase + sw128(o));
            ldmx4(AL[mf], abase + sw128(o + 64));
        }
#pragma unroll
        for (int nb = 0; nb < 2; nb++) {
            unsigned o = (bRowB + wn*32 + nb*16)*128 + bKH + ks*32;
            ldmx4(BH[nb], pbase + sw128(o));
            ldmx4(BL[nb], pbase + sw128(o + 64));
        }
#pragma unroll
        for (int mf = 0; mf < 4; mf++)
#pragma unroll
            for (int nb = 0; nb < 2; nb++)
#pragma unroll
                for (int ns = 0; ns < 2; ns++) {
                    float* c = acc[mf][nb*2 + ns];
                    mma_bf16(c, AH[mf], BH[nb][ns*2], BH[nb][ns*2+1]);
                    mma_bf16(c, AH[mf], BL[nb][ns*2], BL[nb][ns*2+1]);
                    mma_bf16(c, AL[mf], BH[nb][ns*2], BH[nb][ns*2+1]);
                }
    };

    // 3-stage pipeline
    loadA(0, 0); loadB(0, 0); cp_commit();
    loadA(1, 1); loadB(1, 1); cp_commit();
    cp_wait1(); __syncthreads();

    int cur = 0;
    for (int c = 0; c < 64; c++) {
        if (c + 2 < 64) {
            int nb = cur + 2; if (nb >= 3) nb -= 3;
            loadA(c+2, nb); loadB(c+2, nb); cp_commit();
        }
        mma_step(cur, 0);
        mma_step(cur, 1);
        if (c + 2 < 64) cp_wait1(); else cp_wait0();
        __syncthreads();
        if (++cur == 3) cur = 0;
    }

    // epilogue: write bf16 hi/lo split of field
#pragma unroll
    for (int mf = 0; mf < 4; mf++)
#pragma unroll
        for (int nf = 0; nf < 4; nf++) {
            const float* cc = acc[mf][nf];
            int i = i0 + wm*64 + mf*16 + (l >> 2);
            int d = d0 + wn*32 + nf*8 + (l & 3)*2;
            size_t o1 = ((size_t)bk*NQ + i)*DQ + d;
            size_t o2 = o1 + (size_t)8*DQ;
            __nv_bfloat162 h2, l2;
            h2.x = __float2bfloat16(cc[0]); h2.y = __float2bfloat16(cc[1]);
            l2.x = __float2bfloat16(cc[0] - __bfloat162float(h2.x));
            l2.y = __float2bfloat16(cc[1] - __bfloat162float(h2.y));
            *(__nv_bfloat162*)(g_fh + o1) = h2;
            *(__nv_bfloat162*)(g_fl + o1) = l2;
            h2.x = __float2bfloat16(cc[2]); h2.y = __float2bfloat16(cc[3]);
            l2.x = __float2bfloat16(cc[2] - __bfloat162float(h2.x));
            l2.y = __float2bfloat16(cc[3] - __bfloat162float(h2.y));
            *(__nv_bfloat162*)(g_fh + o2) = h2;
            *(__nv_bfloat162*)(g_fl + o2) = l2;
        }
}

// ---------------------------------------------------------------------------
// Kernel C: 64-row i-tile combine + LN (unchanged, passing)
// ---------------------------------------------------------------------------
__global__ __launch_bounds__(256, 1) void combine_mma_kernel(
    const float* __restrict__ gammaP, const float* __restrict__ betaP,
    float* __restrict__ out)
{
    extern __shared__ char smc[];
    const unsigned sb = smem_u32(smc);
    const int t = threadIdx.x, l = t & 31, w = t >> 5;
    const int i0 = blockIdx.x * 64;
    const int b  = blockIdx.y;

    float* rowSum = (float*)(smc + CM_LN);          // 64 x 32
    float* rowSq  = rowSum + 2048;
    float* gammaS = (float*)(smc + CM_GB);
    float* betaS  = gammaS + 512;
    __shared__ float meanS[64], rsS[64];

    for (int u = t; u < 512; u += 256) { gammaS[u] = gammaP[u]; betaS[u] = betaP[u]; }

    float acc[4][8][4];
#pragma unroll
    for (int mf = 0; mf < 4; mf++)
#pragma unroll
        for (int nf = 0; nf < 8; nf++)
#pragma unroll
            for (int q = 0; q < 4; q++) acc[mf][nf][q] = 0.0f;

    auto loadA = [&](int c, int buf) {
        int row = t >> 2, s = t & 3, sel = s >> 1, h = s & 1;
        int k = c >> 5, d0 = (c & 31)*16;
        const __nv_bfloat16* src = (sel ? g_fl : g_fh) +
            ((size_t)(b*KQ + k)*NQ + i0 + row)*DQ + d0 + h*8;
        cp16(sb + CM_A + buf*4096 + sw64row(row, sel*32 + h*16), src);
    };
    auto loadB = [&](int c, int buf) {
        unsigned dst = sb + CM_B + buf*32768;
#pragma unroll
        for (int rr = 0; rr < 2; rr++) {
            int row = t*2 + rr;
            const __nv_bfloat16* srcH = g_cbh + (size_t)row*KDQ + c*16;
            const __nv_bfloat16* srcL = g_cbl + (size_t)row*KDQ + c*16;
            cp16(dst + sw64row(row, 0),  srcH);
            cp16(dst + sw64row(row, 16), srcH + 8);
            cp16(dst + sw64row(row, 32), srcL);
            cp16(dst + sw64row(row, 48), srcL + 8);
        }
    };

    const unsigned aRow = (unsigned)(l & 15);
    const unsigned aH   = (unsigned)((l >> 4)*16);
    const unsigned bRow = (unsigned)((l & 7) + ((l >> 4) & 1)*8);
    const unsigned bH   = (unsigned)(((l >> 3) & 1)*16);

    loadA(0, 0); loadB(0, 0); cp_commit();
    cp_wait0(); __syncthreads();

    for (int c = 0; c < 128; c++) {
        const int cur = c & 1, nxt = cur ^ 1;
        if (c + 1 < 128) { loadA(c+1, nxt); loadB(c+1, nxt); }
        cp_commit();

        const unsigned abase = sb + CM_A + cur*4096;
        const unsigned bbase = sb + CM_B + cur*32768;
        uint32_t AH[4][4], AL[4][4];
#pragma unroll
        for (int mf = 0; mf < 4; mf++) {
            unsigned r = mf*16 + aRow;
            ldmx4(AH[mf], abase + sw64row(r, aH));
            ldmx4(AL[mf], abase + sw64row(r, 32 + aH));
        }
#pragma unroll
        for (int nb = 0; nb < 4; nb++) {
            uint32_t BH[4], BL[4];
            unsigned r = w*64 + nb*16 + bRow;
            ldmx4(BH, bbase + sw64row(r, bH));
            ldmx4(BL, bbase + sw64row(r, 32 + bH));
#pragma unroll
            for (int mf = 0; mf < 4; mf++)
#pragma unroll
                for (int ns = 0; ns < 2; ns++) {
                    float* cc = acc[mf][nb*2 + ns];
                    mma_bf16(cc, AH[mf], BH[ns*2], BH[ns*2+1]);
                    mma_bf16(cc, AH[mf], BL[ns*2], BL[ns*2+1]);
                    mma_bf16(cc, AL[mf], BH[ns*2], BH[ns*2+1]);
                }
        }

        if (c + 1 < 128) { cp_wait0(); }
        __syncthreads();
    }

    // ---- LayerNorm over 64 rows ----
    const int cw = w*4 + (l & 3);
#pragma unroll
    for (int mf = 0; mf < 4; mf++) {
        float sLo = 0.f, sHi = 0.f, qLo = 0.f, qHi = 0.f;
#pragma unroll
        for (int nf = 0; nf < 8; nf++) {
            const float* cc = acc[mf][nf];
            sLo += cc[0] + cc[1];  qLo += cc[0]*cc[0] + cc[1]*cc[1];
            sHi += cc[2] + cc[3];  qHi += cc[2]*cc[2] + cc[3]*cc[3];
        }
        int rLo = mf*16 + (l >> 2), rHi = rLo + 8;
        rowSum[rLo*32 + cw] = sLo;  rowSq[rLo*32 + cw] = qLo;
        rowSum[rHi*32 + cw] = sHi;  rowSq[rHi*32 + cw] = qHi;
    }
    __syncthreads();
#pragma unroll
    for (int rr = 0; rr < 8; rr++) {
        int row = w*8 + rr;
        float s  = rowSum[row*32 + l];
        float s2 = rowSq [row*32 + l];
#pragma unroll
        for (int off = 16; off > 0; off >>= 1) {
            s  += __shfl_xor_sync(0xffffffffu, s,  off);
            s2 += __shfl_xor_sync(0xffffffffu, s2, off);
        }
        if (l == 0) {
            float mean = s * (1.0f/512.0f);
            float var  = s2 * (1.0f/512.0f) - mean*mean;
            meanS[row] = mean;
            rsS[row]   = rsqrtf(var + 1e-5f);
        }
    }
    __syncthreads();

#pragma unroll
    for (int mf = 0; mf < 4; mf++)
#pragma unroll
        for (int nf = 0; nf < 8; nf++) {
            const float* cc = acc[mf][nf];
            int dout = w*64 + nf*8 + (l & 3)*2;
            float g0 = gammaS[dout], g1 = gammaS[dout+1];
            float b0 = betaS[dout],  b1 = betaS[dout+1];
            int rLo = mf*16 + (l >> 2), rHi = rLo + 8;
            float mLo = meanS[rLo], rsLo = rsS[rLo];
            float mHi = meanS[rHi], rsHi = rsS[rHi];
            float* dLo = out + ((size_t)b*NQ + i0 + rLo)*DQ + dout;
            float* dHi = out + ((size_t)b*NQ + i0 + rHi)*DQ + dout;
            *(float2*)dLo = make_float2((cc[0]-mLo)*rsLo*g0 + b0,
                                        (cc[1]-mLo)*rsLo*g1 + b1);
            *(float2*)dHi = make_float2((cc[2]-mHi)*rsHi*g0 + b0,
                                        (cc[3]-mHi)*rsHi*g1 + b1);
        }
}

// ---------------------------------------------------------------------------
extern "C" void kernel_launch(void* const* d_in, const int* in_sizes, int n_in,
                              void* d_out, int out_size)
{
    const float* charge   = (const float*)d_in[0];
    const float* position = (const float*)d_in[1];
    const float* mass     = (const float*)d_in[2];
    const float* lbw      = (const float*)d_in[3];
    const float* Wch      = (const float*)d_in[4];
    const float* Wcb      = (const float*)d_in[5];
    const float* gammaP   = (const float*)d_in[6];
    const float* betaP    = (const float*)d_in[7];
    float* out = (float*)d_out;

    cudaFuncSetAttribute(proj_mma_kernel,
                         cudaFuncAttributeMaxDynamicSharedMemorySize, SMEM_PJ);
    cudaFuncSetAttribute(field_gemm_kernel,
                         cudaFuncAttributeMaxDynamicSharedMemorySize, SMEM_FG);
    cudaFuncSetAttribute(combine_mma_kernel,
                         cudaFuncAttributeMaxDynamicSharedMemorySize, SMEM_COMB);

    split_ch_kernel  <<<(BQ*NQ*DQ)/1024, 256>>>(charge);
    split_cw_kernel  <<<(KDQ*DQ)/1024, 256>>>(Wch);
    split_cb_kernel  <<<(DQ*KDQ)/1024, 256>>>(Wcb);
    proj_mma_kernel  <<<dim3(NQ/128, KDQ/128, BQ), 256, SMEM_PJ>>>(mass);
    wgen_kernel      <<<dim3(NQ/128, NQ/128, BQ), 256>>>(position, lbw);
    field_gemm_kernel<<<dim3(NQ/128, DQ/128, BQ*KQ), 256, SMEM_FG>>>(lbw);
    combine_mma_kernel<<<dim3(NQ/64, BQ), 256, SMEM_COMB>>>(gammaP, betaP, out);
}

// round 11
// speedup vs baseline: 2.8612x; 1.2199x over previous
#include <cuda_runtime.h>
#include <cuda_bf16.h>
#include <cstdint>

// Problem constants
#define BQ 4
#define NQ 2048
#define DQ 512
#define PQ 16
#define KQ 4
#define KDQ (KQ*DQ)

// Scratch
__device__ __nv_bfloat16 g_pT_hi[(size_t)BQ*KQ*DQ*NQ];   // [bk][d][j]  (mass folded in)
__device__ __nv_bfloat16 g_pT_lo[(size_t)BQ*KQ*DQ*NQ];
__device__ __nv_bfloat16 g_fh[(size_t)BQ*KQ*NQ*DQ];      // field bf16 hi  [bk][i][d]
__device__ __nv_bfloat16 g_fl[(size_t)BQ*KQ*NQ*DQ];      // field bf16 lo
__device__ __nv_bfloat16 g_cbh[(size_t)DQ*KDQ];          // W_combine hi [dout][kd]
__device__ __nv_bfloat16 g_cbl[(size_t)DQ*KDQ];          // W_combine lo
__device__ __nv_bfloat16 g_wh[(size_t)BQ*KQ*NQ*NQ];      // weights hi [bk][i][j]
__device__ __nv_bfloat16 g_wl[(size_t)BQ*KQ*NQ*NQ];      // weights lo
__device__ __nv_bfloat16 g_chh[(size_t)BQ*NQ*DQ];        // charge hi [b][j][c]
__device__ __nv_bfloat16 g_chl[(size_t)BQ*NQ*DQ];
__device__ __nv_bfloat16 g_cwh[(size_t)KDQ*DQ];          // W_charge hi [kd][c]
__device__ __nv_bfloat16 g_cwl[(size_t)KDQ*DQ];

// ---------------------------------------------------------------------------
// helpers
// ---------------------------------------------------------------------------
__device__ __forceinline__ unsigned smem_u32(const void* p) {
    return (unsigned)__cvta_generic_to_shared(p);
}
__device__ __forceinline__ void cp16(unsigned dst, const void* src) {
    asm volatile("cp.async.cg.shared.global [%0], [%1], 16;" :: "r"(dst), "l"(src));
}
__device__ __forceinline__ void cp_commit() { asm volatile("cp.async.commit_group;"); }
__device__ __forceinline__ void cp_wait0()  { asm volatile("cp.async.wait_group 0;"); }

__device__ __forceinline__ unsigned sw128(unsigned o) {   // SW128: bits[6:4] ^= bits[9:7]
    return o ^ ((o >> 3) & 0x70u);
}
__device__ __forceinline__ unsigned sw64row(unsigned row, unsigned seg) {
    return row*64u + (seg ^ ((row & 6u) << 3));
}

__device__ __forceinline__ void ldmx4(uint32_t* r, unsigned addr) {
    asm volatile("ldmatrix.sync.aligned.m8n8.x4.shared.b16 {%0,%1,%2,%3}, [%4];"
                 : "=r"(r[0]), "=r"(r[1]), "=r"(r[2]), "=r"(r[3]) : "r"(addr));
}

__device__ __forceinline__ void mma_bf16(float* c, const uint32_t* a,
                                         uint32_t b0, uint32_t b1) {
    asm volatile("mma.sync.aligned.m16n8k16.row.col.f32.bf16.bf16.f32 "
                 "{%0,%1,%2,%3}, {%4,%5,%6,%7}, {%8,%9}, {%0,%1,%2,%3};"
                 : "+f"(c[0]), "+f"(c[1]), "+f"(c[2]), "+f"(c[3])
                 : "r"(a[0]), "r"(a[1]), "r"(a[2]), "r"(a[3]), "r"(b0), "r"(b1));
}

__device__ __forceinline__ uint32_t pack_bf2(__nv_bfloat16 a, __nv_bfloat16 b) {
    return (uint32_t)__bfloat16_as_ushort(a) | ((uint32_t)__bfloat16_as_ushort(b) << 16);
}

// proj kernel smem: loop A 2x16KB | B 2x16KB; epilogue reuses as 128x132 fp32
#define PJ_A   0
#define PJ_B   32768
#define SMEM_PJ 67584

// field GEMM smem: 2-stage, A 2x16KB | B 2x16KB
#define FG_A   0
#define FG_B   32768
#define SMEM_FG 65536

// combine kernel smem layout (64-row i-tile)
#define CM_A   0          // 2 x 4KB
#define CM_B   8192       // 2 x 32KB
#define CM_LN  73728      // rowSum 8KB | rowSq 8KB
#define CM_GB  90112      // gamma 2KB | beta 2KB
#define SMEM_COMB 94208

// ---------------------------------------------------------------------------
// Elementwise bf16 hi/lo split kernels
// ---------------------------------------------------------------------------
__global__ __launch_bounds__(256) void split_ch_kernel(const float* __restrict__ src)
{
    const size_t idx = (size_t)blockIdx.x*1024 + threadIdx.x*4;
    float4 v = *(const float4*)(src + idx);
    float vv[4] = {v.x, v.y, v.z, v.w};
#pragma unroll
    for (int q = 0; q < 4; q++) {
        __nv_bfloat16 h = __float2bfloat16(vv[q]);
        g_chh[idx + q] = h;
        g_chl[idx + q] = __float2bfloat16(vv[q] - __bfloat162float(h));
    }
}
__global__ __launch_bounds__(256) void split_cw_kernel(const float* __restrict__ src)
{
    const size_t idx = (size_t)blockIdx.x*1024 + threadIdx.x*4;
    float4 v = *(const float4*)(src + idx);
    float vv[4] = {v.x, v.y, v.z, v.w};
#pragma unroll
    for (int q = 0; q < 4; q++) {
        __nv_bfloat16 h = __float2bfloat16(vv[q]);
        g_cwh[idx + q] = h;
        g_cwl[idx + q] = __float2bfloat16(vv[q] - __bfloat162float(h));
    }
}
__global__ __launch_bounds__(256) void split_cb_kernel(const float* __restrict__ Wcb)
{
    const size_t idx = (size_t)blockIdx.x*1024 + threadIdx.x*4;
    float4 v = *(const float4*)(Wcb + idx);
    float vv[4] = {v.x, v.y, v.z, v.w};
#pragma unroll
    for (int q = 0; q < 4; q++) {
        __nv_bfloat16 h = __float2bfloat16(vv[q]);
        g_cbh[idx + q] = h;
        g_cbl[idx + q] = __float2bfloat16(vv[q] - __bfloat162float(h));
    }
}

// ---------------------------------------------------------------------------
// Kernel A (tensor, 512 thr / 16 warps 4x4, warp tile 32x32):
// proj = charge @ Wch^T, fused epilogue transpose+mass+split -> g_pT.
// ---------------------------------------------------------------------------
__global__ __launch_bounds__(512, 1) void proj_mma_kernel(const float* __restrict__ mass)
{
    extern __shared__ char smc[];
    const unsigned sb = smem_u32(smc);
    const int t = threadIdx.x, l = t & 31, w = t >> 5;
    const int wm = w & 3, wn = w >> 2;        // 4x4 warp grid
    const int j0 = blockIdx.x * 128, n0 = blockIdx.y * 128;
    const int b = blockIdx.z;

    __shared__ float massS[128];
    if (t < 128) massS[t] = mass[(size_t)b*NQ + j0 + t];

    const unsigned aRowB = (unsigned)(wm*32 + (l & 15));
    const unsigned aKH   = (unsigned)((l >> 4)*16);
    const unsigned bRowB = (unsigned)((l & 7) + ((l >> 4) & 1)*8);
    const unsigned bKH   = (unsigned)(((l >> 3) & 1)*16);

    float acc[2][4][4];
#pragma unroll
    for (int a = 0; a < 2; a++)
#pragma unroll
        for (int n = 0; n < 4; n++)
#pragma unroll
            for (int q = 0; q < 4; q++) acc[a][n][q] = 0.0f;

    auto loadA = [&](int c, int buf) {        // 128 rows x [hi 64B | lo 64B]
        int row = t >> 2, s = t & 3, sel = s >> 1, h = s & 1;
        const __nv_bfloat16* src = (sel ? g_chl : g_chh) +
            ((size_t)b*NQ + j0 + row)*DQ + c*32 + h*16;
        unsigned base = (unsigned)(row*128 + s*32);
        unsigned dst = sb + PJ_A + buf*16384;
        cp16(dst + sw128(base),      src);
        cp16(dst + sw128(base + 16), src + 8);
    };
    auto loadB = [&](int c, int buf) {
        int row = t >> 2, s = t & 3, sel = s >> 1, h = s & 1;
        const __nv_bfloat16* src = (sel ? g_cwl : g_cwh) +
            (size_t)(n0 + row)*DQ + c*32 + h*16;
        unsigned base = (unsigned)(row*128 + s*32);
        unsigned dst = sb + PJ_B + buf*16384;
        cp16(dst + sw128(base),      src);
        cp16(dst + sw128(base + 16), src + 8);
    };

    auto mma_step = [&](int buf, int ks) {
        const unsigned abase = sb + PJ_A + buf*16384;
        const unsigned pbase = sb + PJ_B + buf*16384;
        uint32_t AH[2][4], AL[2][4], BH[2][4], BL[2][4];
#pragma unroll
        for (int mf = 0; mf < 2; mf++) {
            unsigned o = (aRowB + mf*16)*128 + aKH + ks*32;
            ldmx4(AH[mf], abase + sw128(o));
            ldmx4(AL[mf], abase + sw128(o + 64));
        }
#pragma unroll
        for (int nb = 0; nb < 2; nb++) {
            unsigned o = (bRowB + wn*32 + nb*16)*128 + bKH + ks*32;
            ldmx4(BH[nb], pbase + sw128(o));
            ldmx4(BL[nb], pbase + sw128(o + 64));
        }
#pragma unroll
        for (int mf = 0; mf < 2; mf++)
#pragma unroll
            for (int nb = 0; nb < 2; nb++)
#pragma unroll
                for (int ns = 0; ns < 2; ns++) {
                    float* c = acc[mf][nb*2 + ns];
                    mma_bf16(c, AH[mf], BH[nb][ns*2], BH[nb][ns*2+1]);
                    mma_bf16(c, AH[mf], BL[nb][ns*2], BL[nb][ns*2+1]);
                    mma_bf16(c, AL[mf], BH[nb][ns*2], BH[nb][ns*2+1]);
                }
    };

    loadA(0, 0); loadB(0, 0); cp_commit();
    cp_wait0(); __syncthreads();

    for (int c = 0; c < 16; c++) {
        const int cur = c & 1, nxt = cur ^ 1;
        if (c < 15) { loadA(c+1, nxt); loadB(c+1, nxt); cp_commit(); }
        mma_step(cur, 0);
        mma_step(cur, 1);
        if (c < 15) { cp_wait0(); }
        __syncthreads();
    }

    // ---- fused epilogue: stage transposed fp32 tile, then mass+split+store --
    float* tile = (float*)smc;             // 128 cols x 132 (padded)
#pragma unroll
    for (int mf = 0; mf < 2; mf++)
#pragma unroll
        for (int nf = 0; nf < 4; nf++) {
            const float* cc = acc[mf][nf];
            int jl = wm*32 + mf*16 + (l >> 2);
            int cl = wn*32 + nf*8 + (l & 3)*2;
            tile[(cl  )*132 + jl    ] = cc[0];
            tile[(cl+1)*132 + jl    ] = cc[1];
            tile[(cl  )*132 + jl + 8] = cc[2];
            tile[(cl+1)*132 + jl + 8] = cc[3];
        }
    __syncthreads();

    const int jl = l*4;
    const float4 mv = *(const float4*)&massS[jl];
#pragma unroll
    for (int r = 0; r < 8; r++) {
        int cl = w*8 + r;
        float4 v = *(const float4*)&tile[cl*132 + jl];
        float x0 = v.x*mv.x, x1 = v.y*mv.y, x2 = v.z*mv.z, x3 = v.w*mv.w;
        __nv_bfloat16 h0 = __float2bfloat16(x0), h1 = __float2bfloat16(x1);
        __nv_bfloat16 h2 = __float2bfloat16(x2), h3 = __float2bfloat16(x3);
        __nv_bfloat16 l0 = __float2bfloat16(x0 - __bfloat162float(h0));
        __nv_bfloat16 l1 = __float2bfloat16(x1 - __bfloat162float(h1));
        __nv_bfloat16 l2 = __float2bfloat16(x2 - __bfloat162float(h2));
        __nv_bfloat16 l3 = __float2bfloat16(x3 - __bfloat162float(h3));
        int colG = n0 + cl;
        int k = colG >> 9, d = colG & 511;
        size_t ob = ((size_t)(b*KQ + k)*DQ + d)*NQ + j0 + jl;
        *(uint2*)(g_pT_hi + ob) = make_uint2(pack_bf2(h0, h1), pack_bf2(h2, h3));
        *(uint2*)(g_pT_lo + ob) = make_uint2(pack_bf2(l0, l1), pack_bf2(l2, l3));
    }
}

// ---------------------------------------------------------------------------
// Kernel W: weight generation (unchanged; equal-bandwidth slices skipped)
// ---------------------------------------------------------------------------
__global__ __launch_bounds__(256) void wgen_kernel(
    const float* __restrict__ position, const float* __restrict__ lbw)
{
    __shared__ float posI[128*16];
    const int b = blockIdx.z, i0 = blockIdx.y*128, j0 = blockIdx.x*128;
    const int t = threadIdx.x;

    for (int u = t; u < 512; u += 256) {
        int r = u >> 2, q = u & 3;
        *(float4*)&posI[r*16 + q*4] =
            *(const float4*)(position + ((size_t)b*NQ + i0 + r)*PQ + q*4);
    }

    float negc[4];
#pragma unroll
    for (int k = 0; k < 4; k++) negc[k] = -1.0f/(2.0f*__expf(lbw[k]) + 1e-8f);
    const bool eq[4] = {false, negc[1] == negc[0], negc[2] == negc[0], negc[3] == negc[0]};

    const int jp = (t & 63)*2;
    const int ig = t >> 6;

    float pj[32];
#pragma unroll
    for (int u2 = 0; u2 < 2; u2++) {
        const float* p = position + ((size_t)b*NQ + j0 + jp + u2)*PQ;
#pragma unroll
        for (int q = 0; q < 16; q += 4) {
            float4 v = *(const float4*)(p + q);
            pj[u2*16+q] = v.x; pj[u2*16+q+1] = v.y;
            pj[u2*16+q+2] = v.z; pj[u2*16+q+3] = v.w;
        }
    }
    __syncthreads();

    for (int ii = 0; ii < 32; ii++) {
        const int i = ig*32 + ii;
        const float* pi = &posI[i*16];
        float d2a = 0.f, d2b = 0.f;
#pragma unroll
        for (int q = 0; q < 16; q++) {
            float piq = pi[q];
            float da = piq - pj[q], db = piq - pj[16+q];
            d2a = fmaf(da, da, d2a); d2b = fmaf(db, db, d2b);
        }
#pragma unroll
        for (int k = 0; k < 4; k++) {
            if (k > 0 && eq[k]) continue;
            float ea = __expf(d2a*negc[k]);
            float eb = __expf(d2b*negc[k]);
            __nv_bfloat162 h2, l2;
            h2.x = __float2bfloat16(ea);
            h2.y = __float2bfloat16(eb);
            l2.x = __float2bfloat16(ea - __bfloat162float(h2.x));
            l2.y = __float2bfloat16(eb - __bfloat162float(h2.y));
            size_t off = ((size_t)(b*KQ + k)*NQ + i0 + i)*NQ + j0 + jp;
            *(__nv_bfloat162*)(g_wh + off) = h2;
            *(__nv_bfloat162*)(g_wl + off) = l2;
        }
    }
}

// ---------------------------------------------------------------------------
// Kernel B (512 thr / 16 warps 4x4, warp tile 32x32): field GEMM, 2-stage.
// A-base folds equal-bandwidth k to slice 0 (L2 sharing).
// ---------------------------------------------------------------------------
__global__ __launch_bounds__(512, 1) void field_gemm_kernel(const float* __restrict__ lbw)
{
    extern __shared__ char smc[];
    const unsigned sb = smem_u32(smc);
    const int t = threadIdx.x, l = t & 31, w = t >> 5;
    const int wm = w & 3, wn = w >> 2;
    const int i0 = blockIdx.x * 128, d0 = blockIdx.y * 128;
    const int bk = blockIdx.z, b = bk >> 2, k = bk & 3;

    const float nc0 = -1.0f/(2.0f*__expf(lbw[0]) + 1e-8f);
    const float nck = -1.0f/(2.0f*__expf(lbw[k]) + 1e-8f);
    const int ksrc = (nck == nc0) ? 0 : k;
    const size_t wbase_g = (size_t)(b*KQ + ksrc)*NQ*NQ;

    const unsigned aRowB = (unsigned)(wm*32 + (l & 15));
    const unsigned aKH   = (unsigned)((l >> 4)*16);
    const unsigned bRowB = (unsigned)((l & 7) + ((l >> 4) & 1)*8);
    const unsigned bKH   = (unsigned)(((l >> 3) & 1)*16);

    float acc[2][4][4];
#pragma unroll
    for (int a = 0; a < 2; a++)
#pragma unroll
        for (int n = 0; n < 4; n++)
#pragma unroll
            for (int q = 0; q < 4; q++) acc[a][n][q] = 0.0f;

    auto loadA = [&](int c, int buf) {
        int row = t >> 2, s = t & 3, sel = s >> 1, h = s & 1;
        const __nv_bfloat16* src = (sel ? g_wl : g_wh) +
            wbase_g + (size_t)(i0 + row)*NQ + c*32 + h*16;
        unsigned base = (unsigned)(row*128 + s*32);
        unsigned dst = sb + FG_A + buf*16384;
        cp16(dst + sw128(base),      src);
        cp16(dst + sw128(base + 16), src + 8);
    };
    auto loadB = [&](int c, int buf) {
        int row = t >> 2, s = t & 3, sel = s >> 1, h = s & 1;
        const __nv_bfloat16* src = (sel ? g_pT_lo : g_pT_hi) +
            ((size_t)bk*DQ + d0 + row)*NQ + c*32 + h*16;
        unsigned base = (unsigned)(row*128 + s*32);
        unsigned dst = sb + FG_B + buf*16384;
        cp16(dst + sw128(base),      src);
        cp16(dst + sw128(base + 16), src + 8);
    };

    auto mma_step = [&](int buf, int ks) {
        const unsigned abase = sb + FG_A + buf*16384;
        const unsigned pbase = sb + FG_B + buf*16384;
        uint32_t AH[2][4], AL[2][4], BH[2][4], BL[2][4];
#pragma unroll
        for (int mf = 0; mf < 2; mf++) {
            unsigned o = (aRowB + mf*16)*128 + aKH + ks*32;
            ldmx4(AH[mf], abase + sw128(o));
            ldmx4(AL[mf], abase + sw128(o + 64));
        }
#pragma unroll
        for (int nb = 0; nb < 2; nb++) {
            unsigned o = (bRowB + wn*32 + nb*16)*128 + bKH + ks*32;
            ldmx4(BH[nb], pbase + sw128(o));
            ldmx4(BL[nb], pbase + sw128(o + 64));
        }
#pragma unroll
        for (int mf = 0; mf < 2; mf++)
#pragma unroll
            for (int nb = 0; nb < 2; nb++)
#pragma unroll
                for (int ns = 0; ns < 2; ns++) {
                    float* c = acc[mf][nb*2 + ns];
                    mma_bf16(c, AH[mf], BH[nb][ns*2], BH[nb][ns*2+1]);
                    mma_bf16(c, AH[mf], BL[nb][ns*2], BL[nb][ns*2+1]);
                    mma_bf16(c, AL[mf], BH[nb][ns*2], BH[nb][ns*2+1]);
                }
    };

    loadA(0, 0); loadB(0, 0); cp_commit();
    cp_wait0(); __syncthreads();

    for (int c = 0; c < 64; c++) {
        const int cur = c & 1, nxt = cur ^ 1;
        if (c < 63) { loadA(c+1, nxt); loadB(c+1, nxt); cp_commit(); }
        mma_step(cur, 0);
        mma_step(cur, 1);
        if (c < 63) { cp_wait0(); }
        __syncthreads();
    }

    // epilogue: write bf16 hi/lo split of field
#pragma unroll
    for (int mf = 0; mf < 2; mf++)
#pragma unroll
        for (int nf = 0; nf < 4; nf++) {
            const float* cc = acc[mf][nf];
            int i = i0 + wm*32 + mf*16 + (l >> 2);
            int d = d0 + wn*32 + nf*8 + (l & 3)*2;
            size_t o1 = ((size_t)bk*NQ + i)*DQ + d;
            size_t o2 = o1 + (size_t)8*DQ;
            __nv_bfloat162 h2, l2;
            h2.x = __float2bfloat16(cc[0]); h2.y = __float2bfloat16(cc[1]);
            l2.x = __float2bfloat16(cc[0] - __bfloat162float(h2.x));
            l2.y = __float2bfloat16(cc[1] - __bfloat162float(h2.y));
            *(__nv_bfloat162*)(g_fh + o1) = h2;
            *(__nv_bfloat162*)(g_fl + o1) = l2;
            h2.x = __float2bfloat16(cc[2]); h2.y = __float2bfloat16(cc[3]);
            l2.x = __float2bfloat16(cc[2] - __bfloat162float(h2.x));
            l2.y = __float2bfloat16(cc[3] - __bfloat162float(h2.y));
            *(__nv_bfloat162*)(g_fh + o2) = h2;
            *(__nv_bfloat162*)(g_fl + o2) = l2;
        }
}

// ---------------------------------------------------------------------------
// Kernel C: 64-row i-tile combine + LN (unchanged, passing)
// ---------------------------------------------------------------------------
__global__ __launch_bounds__(256, 1) void combine_mma_kernel(
    const float* __restrict__ gammaP, const float* __restrict__ betaP,
    float* __restrict__ out)
{
    extern __shared__ char smc[];
    const unsigned sb = smem_u32(smc);
    const int t = threadIdx.x, l = t & 31, w = t >> 5;
    const int i0 = blockIdx.x * 64;
    const int b  = blockIdx.y;

    float* rowSum = (float*)(smc + CM_LN);          // 64 x 32
    float* rowSq  = rowSum + 2048;
    float* gammaS = (float*)(smc + CM_GB);
    float* betaS  = gammaS + 512;
    __shared__ float meanS[64], rsS[64];

    for (int u = t; u < 512; u += 256) { gammaS[u] = gammaP[u]; betaS[u] = betaP[u]; }

    float acc[4][8][4];
#pragma unroll
    for (int mf = 0; mf < 4; mf++)
#pragma unroll
        for (int nf = 0; nf < 8; nf++)
#pragma unroll
            for (int q = 0; q < 4; q++) acc[mf][nf][q] = 0.0f;

    auto loadA = [&](int c, int buf) {
        int row = t >> 2, s = t & 3, sel = s >> 1, h = s & 1;
        int k = c >> 5, d0 = (c & 31)*16;
        const __nv_bfloat16* src = (sel ? g_fl : g_fh) +
            ((size_t)(b*KQ + k)*NQ + i0 + row)*DQ + d0 + h*8;
        cp16(sb + CM_A + buf*4096 + sw64row(row, sel*32 + h*16), src);
    };
    auto loadB = [&](int c, int buf) {
        unsigned dst = sb + CM_B + buf*32768;
#pragma unroll
        for (int rr = 0; rr < 2; rr++) {
            int row = t*2 + rr;
            const __nv_bfloat16* srcH = g_cbh + (size_t)row*KDQ + c*16;
            const __nv_bfloat16* srcL = g_cbl + (size_t)row*KDQ + c*16;
            cp16(dst + sw64row(row, 0),  srcH);
            cp16(dst + sw64row(row, 16), srcH + 8);
            cp16(dst + sw64row(row, 32), srcL);
            cp16(dst + sw64row(row, 48), srcL + 8);
        }
    };

    const unsigned aRow = (unsigned)(l & 15);
    const unsigned aH   = (unsigned)((l >> 4)*16);
    const unsigned bRow = (unsigned)((l & 7) + ((l >> 4) & 1)*8);
    const unsigned bH   = (unsigned)(((l >> 3) & 1)*16);

    loadA(0, 0); loadB(0, 0); cp_commit();
    cp_wait0(); __syncthreads();

    for (int c = 0; c < 128; c++) {
        const int cur = c & 1, nxt = cur ^ 1;
        if (c + 1 < 128) { loadA(c+1, nxt); loadB(c+1, nxt); }
        cp_commit();

        const unsigned abase = sb + CM_A + cur*4096;
        const unsigned bbase = sb + CM_B + cur*32768;
        uint32_t AH[4][4], AL[4][4];
#pragma unroll
        for (int mf = 0; mf < 4; mf++) {
            unsigned r = mf*16 + aRow;
            ldmx4(AH[mf], abase + sw64row(r, aH));
            ldmx4(AL[mf], abase + sw64row(r, 32 + aH));
        }
#pragma unroll
        for (int nb = 0; nb < 4; nb++) {
            uint32_t BH[4], BL[4];
            unsigned r = w*64 + nb*16 + bRow;
            ldmx4(BH, bbase + sw64row(r, bH));
            ldmx4(BL, bbase + sw64row(r, 32 + bH));
#pragma unroll
            for (int mf = 0; mf < 4; mf++)
#pragma unroll
                for (int ns = 0; ns < 2; ns++) {
                    float* cc = acc[mf][nb*2 + ns];
                    mma_bf16(cc, AH[mf], BH[ns*2], BH[ns*2+1]);
                    mma_bf16(cc, AH[mf], BL[ns*2], BL[ns*2+1]);
                    mma_bf16(cc, AL[mf], BH[ns*2], BH[ns*2+1]);
                }
        }

        if (c + 1 < 128) { cp_wait0(); }
        __syncthreads();
    }

    // ---- LayerNorm over 64 rows ----
    const int cw = w*4 + (l & 3);
#pragma unroll
    for (int mf = 0; mf < 4; mf++) {
        float sLo = 0.f, sHi = 0.f, qLo = 0.f, qHi = 0.f;
#pragma unroll
        for (int nf = 0; nf < 8; nf++) {
            const float* cc = acc[mf][nf];
            sLo += cc[0] + cc[1];  qLo += cc[0]*cc[0] + cc[1]*cc[1];
            sHi += cc[2] + cc[3];  qHi += cc[2]*cc[2] + cc[3]*cc[3];
        }
        int rLo = mf*16 + (l >> 2), rHi = rLo + 8;
        rowSum[rLo*32 + cw] = sLo;  rowSq[rLo*32 + cw] = qLo;
        rowSum[rHi*32 + cw] = sHi;  rowSq[rHi*32 + cw] = qHi;
    }
    __syncthreads();
#pragma unroll
    for (int rr = 0; rr < 8; rr++) {
        int row = w*8 + rr;
        float s  = rowSum[row*32 + l];
        float s2 = rowSq [row*32 + l];
#pragma unroll
        for (int off = 16; off > 0; off >>= 1) {
            s  += __shfl_xor_sync(0xffffffffu, s,  off);
            s2 += __shfl_xor_sync(0xffffffffu, s2, off);
        }
        if (l == 0) {
            float mean = s * (1.0f/512.0f);
            float var  = s2 * (1.0f/512.0f) - mean*mean;
            meanS[row] = mean;
            rsS[row]   = rsqrtf(var + 1e-5f);
        }
    }
    __syncthreads();

#pragma unroll
    for (int mf = 0; mf < 4; mf++)
#pragma unroll
        for (int nf = 0; nf < 8; nf++) {
            const float* cc = acc[mf][nf];
            int dout = w*64 + nf*8 + (l & 3)*2;
            float g0 = gammaS[dout], g1 = gammaS[dout+1];
            float b0 = betaS[dout],  b1 = betaS[dout+1];
            int rLo = mf*16 + (l >> 2), rHi = rLo + 8;
            float mLo = meanS[rLo], rsLo = rsS[rLo];
            float mHi = meanS[rHi], rsHi = rsS[rHi];
            float* dLo = out + ((size_t)b*NQ + i0 + rLo)*DQ + dout;
            float* dHi = out + ((size_t)b*NQ + i0 + rHi)*DQ + dout;
            *(float2*)dLo = make_float2((cc[0]-mLo)*rsLo*g0 + b0,
                                        (cc[1]-mLo)*rsLo*g1 + b1);
            *(float2*)dHi = make_float2((cc[2]-mHi)*rsHi*g0 + b0,
                                        (cc[3]-mHi)*rsHi*g1 + b1);
        }
}

// ---------------------------------------------------------------------------
extern "C" void kernel_launch(void* const* d_in, const int* in_sizes, int n_in,
                              void* d_out, int out_size)
{
    const float* charge   = (const float*)d_in[0];
    const float* position = (const float*)d_in[1];
    const float* mass     = (const float*)d_in[2];
    const float* lbw      = (const float*)d_in[3];
    const float* Wch      = (const float*)d_in[4];
    const float* Wcb      = (const float*)d_in[5];
    const float* gammaP   = (const float*)d_in[6];
    const float* betaP    = (const float*)d_in[7];
    float* out = (float*)d_out;

    cudaFuncSetAttribute(proj_mma_kernel,
                         cudaFuncAttributeMaxDynamicSharedMemorySize, SMEM_PJ);
    cudaFuncSetAttribute(field_gemm_kernel,
                         cudaFuncAttributeMaxDynamicSharedMemorySize, SMEM_FG);
    cudaFuncSetAttribute(combine_mma_kernel,
                         cudaFuncAttributeMaxDynamicSharedMemorySize, SMEM_COMB);

    split_ch_kernel  <<<(BQ*NQ*DQ)/1024, 256>>>(charge);
    split_cw_kernel  <<<(KDQ*DQ)/1024, 256>>>(Wch);
    split_cb_kernel  <<<(DQ*KDQ)/1024, 256>>>(Wcb);
    proj_mma_kernel  <<<dim3(NQ/128, KDQ/128, BQ), 512, SMEM_PJ>>>(mass);
    wgen_kernel      <<<dim3(NQ/128, NQ/128, BQ), 256>>>(position, lbw);
    field_gemm_kernel<<<dim3(NQ/128, DQ/128, BQ*KQ), 512, SMEM_FG>>>(lbw);
    combine_mma_kernel<<<dim3(NQ/64, BQ), 256, SMEM_COMB>>>(gammaP, betaP, out);
}